// round 1
// baseline (speedup 1.0000x reference)
#include <cuda_runtime.h>
#include <math.h>

#define B_  2
#define N_  16384
#define M_  2048
#define D_  256
#define R_  (B_*N_)    // 32768 rows of p_features
#define RQ_ (B_*M_)    // 4096  rows of v_features
#define TILE 64
#define KT   16

// ---- scratch (device globals: allocation-free per harness rules) ----
__device__ __align__(16) float g_r[R_*3];                       // relu(LN(dist@Wp1)) per row
__device__ __align__(16) float g_kpv[(size_t)R_*D_];            // k + pv
__device__ __align__(16) float g_v[(size_t)R_*D_];              // v
__device__ __align__(16) float g_q[(size_t)RQ_*D_];             // q
__device__ __align__(16) float g_logits[(size_t)B_*M_*N_];      // 256 MB
__device__ __align__(16) float g_cstat[B_*N_];                  // colmax + log(colsum)

// ---------------------------------------------------------------------------
// K0: per-row positional path: dist -> Linear(3,3) -> LayerNorm(3) -> ReLU
// ---------------------------------------------------------------------------
__global__ void pv_relu_kernel(const float* __restrict__ p_xyz,
                               const float* __restrict__ v_xyz,
                               const float* __restrict__ Wp1,
                               const float* __restrict__ bp1,
                               const float* __restrict__ ln_w,
                               const float* __restrict__ ln_b)
{
    int idx = blockIdx.x * blockDim.x + threadIdx.x;
    if (idx >= R_) return;
    int b = idx / N_;
    float d0 = fabsf(p_xyz[idx*3+0] - v_xyz[b*3+0]);
    float d1 = fabsf(p_xyz[idx*3+1] - v_xyz[b*3+1]);
    float d2 = fabsf(p_xyz[idx*3+2] - v_xyz[b*3+2]);

    float h0 = d0*Wp1[0] + d1*Wp1[3] + d2*Wp1[6] + bp1[0];
    float h1 = d0*Wp1[1] + d1*Wp1[4] + d2*Wp1[7] + bp1[1];
    float h2 = d0*Wp1[2] + d1*Wp1[5] + d2*Wp1[8] + bp1[2];

    float mu  = (h0 + h1 + h2) * (1.0f/3.0f);
    float e0 = h0 - mu, e1 = h1 - mu, e2 = h2 - mu;
    float var = (e0*e0 + e1*e1 + e2*e2) * (1.0f/3.0f);
    float inv = rsqrtf(var + 1e-5f);

    float r0 = fmaxf(e0*inv*ln_w[0] + ln_b[0], 0.0f);
    float r1 = fmaxf(e1*inv*ln_w[1] + ln_b[1], 0.0f);
    float r2 = fmaxf(e2*inv*ln_w[2] + ln_b[2], 0.0f);

    g_r[idx*3+0] = r0;
    g_r[idx*3+1] = r1;
    g_r[idx*3+2] = r2;
}

// ---------------------------------------------------------------------------
// K1: fused K/V projection GEMM: rows of p_features [R_,256] x Wk / Wv.
// Epilogue adds bk + pv (r @ Wp2 + bp2) to K, bv to V. 64x64 tiles, 4x4 micro.
// ---------------------------------------------------------------------------
__global__ void __launch_bounds__(256)
kv_gemm_kernel(const float* __restrict__ P,
               const float* __restrict__ Wk, const float* __restrict__ bk,
               const float* __restrict__ Wv, const float* __restrict__ bv,
               const float* __restrict__ Wp2, const float* __restrict__ bp2)
{
    __shared__ float As[KT][TILE+1];
    __shared__ float Bk[KT][TILE];
    __shared__ float Bv[KT][TILE];

    int t = threadIdx.x;
    int tx = t & 15, ty = t >> 4;
    int c0 = blockIdx.x * TILE;
    int r0 = blockIdx.y * TILE;

    float accK[4][4] = {};
    float accV[4][4] = {};

    for (int k0 = 0; k0 < D_; k0 += KT) {
        {   // A tile (transposed into smem)
            int row = t >> 2, seg = t & 3;
            float4 a = *reinterpret_cast<const float4*>(&P[(size_t)(r0+row)*D_ + k0 + seg*4]);
            As[seg*4+0][row] = a.x; As[seg*4+1][row] = a.y;
            As[seg*4+2][row] = a.z; As[seg*4+3][row] = a.w;
        }
        {   // W tiles (already [k][c])
            int row = t >> 4, seg = t & 15;
            *reinterpret_cast<float4*>(&Bk[row][seg*4]) =
                *reinterpret_cast<const float4*>(&Wk[(size_t)(k0+row)*D_ + c0 + seg*4]);
            *reinterpret_cast<float4*>(&Bv[row][seg*4]) =
                *reinterpret_cast<const float4*>(&Wv[(size_t)(k0+row)*D_ + c0 + seg*4]);
        }
        __syncthreads();
        #pragma unroll
        for (int kk = 0; kk < KT; kk++) {
            float a[4], wk[4], wv[4];
            #pragma unroll
            for (int i = 0; i < 4; i++) a[i] = As[kk][ty*4+i];
            #pragma unroll
            for (int j = 0; j < 4; j++) { wk[j] = Bk[kk][tx*4+j]; wv[j] = Bv[kk][tx*4+j]; }
            #pragma unroll
            for (int i = 0; i < 4; i++)
                #pragma unroll
                for (int j = 0; j < 4; j++) {
                    accK[i][j] += a[i]*wk[j];
                    accV[i][j] += a[i]*wv[j];
                }
        }
        __syncthreads();
    }

    #pragma unroll
    for (int i = 0; i < 4; i++) {
        int r = r0 + ty*4 + i;
        float q0 = g_r[r*3+0], q1 = g_r[r*3+1], q2 = g_r[r*3+2];
        #pragma unroll
        for (int j = 0; j < 4; j++) {
            int c = c0 + tx*4 + j;
            float pv = q0*Wp2[c] + q1*Wp2[D_+c] + q2*Wp2[2*D_+c] + bp2[c];
            g_kpv[(size_t)r*D_ + c] = accK[i][j] + bk[c] + pv;
            g_v  [(size_t)r*D_ + c] = accV[i][j] + bv[c];
        }
    }
}

// ---------------------------------------------------------------------------
// K2: Q projection GEMM: v_features [RQ_,256] x Wq + bq -> g_q
// ---------------------------------------------------------------------------
__global__ void __launch_bounds__(256)
q_gemm_kernel(const float* __restrict__ X, const float* __restrict__ W,
              const float* __restrict__ bias)
{
    __shared__ float As[KT][TILE+1];
    __shared__ float Bs[KT][TILE];

    int t = threadIdx.x;
    int tx = t & 15, ty = t >> 4;
    int c0 = blockIdx.x * TILE;
    int r0 = blockIdx.y * TILE;
    float acc[4][4] = {};

    for (int k0 = 0; k0 < D_; k0 += KT) {
        {
            int row = t >> 2, seg = t & 3;
            float4 a = *reinterpret_cast<const float4*>(&X[(size_t)(r0+row)*D_ + k0 + seg*4]);
            As[seg*4+0][row] = a.x; As[seg*4+1][row] = a.y;
            As[seg*4+2][row] = a.z; As[seg*4+3][row] = a.w;
        }
        {
            int row = t >> 4, seg = t & 15;
            *reinterpret_cast<float4*>(&Bs[row][seg*4]) =
                *reinterpret_cast<const float4*>(&W[(size_t)(k0+row)*D_ + c0 + seg*4]);
        }
        __syncthreads();
        #pragma unroll
        for (int kk = 0; kk < KT; kk++) {
            float a[4], bb[4];
            #pragma unroll
            for (int i = 0; i < 4; i++) a[i] = As[kk][ty*4+i];
            #pragma unroll
            for (int j = 0; j < 4; j++) bb[j] = Bs[kk][tx*4+j];
            #pragma unroll
            for (int i = 0; i < 4; i++)
                #pragma unroll
                for (int j = 0; j < 4; j++) acc[i][j] += a[i]*bb[j];
        }
        __syncthreads();
    }

    #pragma unroll
    for (int i = 0; i < 4; i++) {
        int r = r0 + ty*4 + i;
        #pragma unroll
        for (int j = 0; j < 4; j++) {
            int c = c0 + tx*4 + j;
            g_q[(size_t)r*D_ + c] = acc[i][j] + bias[c];
        }
    }
}

// ---------------------------------------------------------------------------
// K3: logits[b,m,n] = scale * dot(q[b,m,:], kpv[b,n,:])   (NT GEMM, K=256)
// ---------------------------------------------------------------------------
__global__ void __launch_bounds__(256)
logits_gemm_kernel()
{
    int b = blockIdx.z;
    const float* Q = g_q   + (size_t)b*M_*D_;
    const float* K = g_kpv + (size_t)b*N_*D_;
    float*       L = g_logits + (size_t)b*M_*N_;

    __shared__ float As[KT][TILE+1];
    __shared__ float Bs[KT][TILE+1];

    int t = threadIdx.x;
    int tx = t & 15, ty = t >> 4;
    int n0 = blockIdx.x * TILE;
    int m0 = blockIdx.y * TILE;
    float acc[4][4] = {};

    for (int k0 = 0; k0 < D_; k0 += KT) {
        int row = t >> 2, seg = t & 3;
        float4 a = *reinterpret_cast<const float4*>(&Q[(size_t)(m0+row)*D_ + k0 + seg*4]);
        As[seg*4+0][row] = a.x; As[seg*4+1][row] = a.y;
        As[seg*4+2][row] = a.z; As[seg*4+3][row] = a.w;
        float4 bb = *reinterpret_cast<const float4*>(&K[(size_t)(n0+row)*D_ + k0 + seg*4]);
        Bs[seg*4+0][row] = bb.x; Bs[seg*4+1][row] = bb.y;
        Bs[seg*4+2][row] = bb.z; Bs[seg*4+3][row] = bb.w;
        __syncthreads();
        #pragma unroll
        for (int kk = 0; kk < KT; kk++) {
            float av[4], bv[4];
            #pragma unroll
            for (int i = 0; i < 4; i++) av[i] = As[kk][ty*4+i];
            #pragma unroll
            for (int j = 0; j < 4; j++) bv[j] = Bs[kk][tx*4+j];
            #pragma unroll
            for (int i = 0; i < 4; i++)
                #pragma unroll
                for (int j = 0; j < 4; j++) acc[i][j] += av[i]*bv[j];
        }
        __syncthreads();
    }

    const float scale = 0.0625f;  // 1/sqrt(256)
    #pragma unroll
    for (int i = 0; i < 4; i++) {
        int m = m0 + ty*4 + i;
        #pragma unroll
        for (int j = 0; j < 4; j++) {
            int n = n0 + tx*4 + j;
            L[(size_t)m*N_ + n] = acc[i][j] * scale;
        }
    }
}

// ---------------------------------------------------------------------------
// K4: column-wise (over m, axis=-2) softmax stats: cstat = max + log(sumexp)
// blockDim = (32 columns, 8 m-slices)
// ---------------------------------------------------------------------------
__global__ void col_stats_kernel()
{
    __shared__ float red[8][33];
    int tx = threadIdx.x;          // column within block
    int ty = threadIdx.y;          // m-slice
    int col = blockIdx.x * 32 + tx;           // 0 .. B_*N_-1
    int b = col / N_;
    int n = col - b * N_;
    const float* L = g_logits + (size_t)b*M_*N_ + n;

    float mx = -1e30f;
    #pragma unroll 4
    for (int m = ty; m < M_; m += 8)
        mx = fmaxf(mx, L[(size_t)m*N_]);
    red[ty][tx] = mx;
    __syncthreads();
    if (ty == 0) {
        #pragma unroll
        for (int u = 1; u < 8; u++) mx = fmaxf(mx, red[u][tx]);
        red[0][tx] = mx;
    }
    __syncthreads();
    mx = red[0][tx];

    float s = 0.0f;
    #pragma unroll 4
    for (int m = ty; m < M_; m += 8)
        s += __expf(L[(size_t)m*N_] - mx);
    __syncthreads();
    red[ty][tx] = s;
    __syncthreads();
    if (ty == 0) {
        #pragma unroll
        for (int u = 1; u < 8; u++) s += red[u][tx];
        g_cstat[col] = mx + __logf(s);
    }
}

// ---------------------------------------------------------------------------
// K5: res[b,m,d] = sum_n exp(logits - cstat[n]) * v[b,n,d]; out = res + v_feat
// Weights are exponentiated on-the-fly during the smem tile load.
// ---------------------------------------------------------------------------
__global__ void __launch_bounds__(256)
wv_gemm_kernel(const float* __restrict__ Vf, float* __restrict__ out)
{
    int b = blockIdx.z;
    const float* L  = g_logits + (size_t)b*M_*N_;
    const float* V  = g_v      + (size_t)b*N_*D_;
    const float* CS = g_cstat  + (size_t)b*N_;

    __shared__ float Ws[KT][TILE+1];
    __shared__ float Vs[KT][TILE];

    int t = threadIdx.x;
    int tx = t & 15, ty = t >> 4;
    int d0 = blockIdx.x * TILE;
    int m0 = blockIdx.y * TILE;
    float acc[4][4] = {};

    for (int n0 = 0; n0 < N_; n0 += KT) {
        {
            int row = t >> 2, seg = t & 3;
            int nb = n0 + seg*4;
            float4 l4 = *reinterpret_cast<const float4*>(&L[(size_t)(m0+row)*N_ + nb]);
            Ws[seg*4+0][row] = __expf(l4.x - CS[nb+0]);
            Ws[seg*4+1][row] = __expf(l4.y - CS[nb+1]);
            Ws[seg*4+2][row] = __expf(l4.z - CS[nb+2]);
            Ws[seg*4+3][row] = __expf(l4.w - CS[nb+3]);
        }
        {
            int row = t >> 4, seg = t & 15;
            *reinterpret_cast<float4*>(&Vs[row][seg*4]) =
                *reinterpret_cast<const float4*>(&V[(size_t)(n0+row)*D_ + d0 + seg*4]);
        }
        __syncthreads();
        #pragma unroll
        for (int kk = 0; kk < KT; kk++) {
            float w[4], vv[4];
            #pragma unroll
            for (int i = 0; i < 4; i++) w[i] = Ws[kk][ty*4+i];
            #pragma unroll
            for (int j = 0; j < 4; j++) vv[j] = Vs[kk][tx*4+j];
            #pragma unroll
            for (int i = 0; i < 4; i++)
                #pragma unroll
                for (int j = 0; j < 4; j++) acc[i][j] += w[i]*vv[j];
        }
        __syncthreads();
    }

    #pragma unroll
    for (int i = 0; i < 4; i++) {
        int m = m0 + ty*4 + i;
        #pragma unroll
        for (int j = 0; j < 4; j++) {
            int d = d0 + tx*4 + j;
            size_t o = (size_t)(b*M_ + m)*D_ + d;
            out[o] = acc[i][j] + Vf[o];
        }
    }
}

// ---------------------------------------------------------------------------
// Launcher
// ---------------------------------------------------------------------------
extern "C" void kernel_launch(void* const* d_in, const int* in_sizes, int n_in,
                              void* d_out, int out_size)
{
    const float* p_xyz      = (const float*)d_in[0];
    const float* v_xyz      = (const float*)d_in[1];
    const float* p_features = (const float*)d_in[2];
    const float* v_features = (const float*)d_in[3];
    const float* Wq  = (const float*)d_in[4];
    const float* bq  = (const float*)d_in[5];
    const float* Wk  = (const float*)d_in[6];
    const float* bk  = (const float*)d_in[7];
    const float* Wv  = (const float*)d_in[8];
    const float* bv  = (const float*)d_in[9];
    const float* Wp1 = (const float*)d_in[10];
    const float* bp1 = (const float*)d_in[11];
    const float* ln_w = (const float*)d_in[12];
    const float* ln_b = (const float*)d_in[13];
    const float* Wp2 = (const float*)d_in[14];
    const float* bp2 = (const float*)d_in[15];
    float* out = (float*)d_out;

    // K0: positional path
    pv_relu_kernel<<<R_/256, 256>>>(p_xyz, v_xyz, Wp1, bp1, ln_w, ln_b);

    // K1: fused K/V projection (+pv epilogue)
    kv_gemm_kernel<<<dim3(D_/TILE, R_/TILE), 256>>>(p_features, Wk, bk, Wv, bv, Wp2, bp2);

    // K2: Q projection
    q_gemm_kernel<<<dim3(D_/TILE, RQ_/TILE), 256>>>(v_features, Wq, bq);

    // K3: logits
    logits_gemm_kernel<<<dim3(N_/TILE, M_/TILE, B_), 256>>>();

    // K4: softmax stats over m (axis=-2)
    col_stats_kernel<<<(B_*N_)/32, dim3(32, 8)>>>();

    // K5: weighted value + residual
    wv_gemm_kernel<<<dim3(D_/TILE, M_/TILE, B_), 256>>>(v_features, out);
}

// round 4
// speedup vs baseline: 2.7078x; 2.7078x over previous
#include <cuda_runtime.h>
#include <cuda_fp16.h>
#include <stdint.h>
#include <math.h>

#define B_  2
#define N_  16384
#define M_  2048
#define D_  256
#define R_  (B_*N_)
#define RQ_ (B_*M_)
#define NSPLIT 8
#define KR_ (N_/NSPLIT)          // 2048 contraction per wv split
#define STAGE_BYTES 32768        // Ah(8K) Al(8K) Bh(8K) Bl(8K)
#define DYN_SMEM (2*STAGE_BYTES)

// ======================= device scratch =====================================
__device__ __align__(16) float  g_r[R_*3];
__device__ __align__(16) __half g_ph [(size_t)R_*D_],  g_pl [(size_t)R_*D_];
__device__ __align__(16) __half g_vfh[(size_t)RQ_*D_], g_vfl[(size_t)RQ_*D_];
__device__ __align__(16) __half g_wqTh[D_*D_], g_wqTl[D_*D_];
__device__ __align__(16) __half g_wkTh[D_*D_], g_wkTl[D_*D_];
__device__ __align__(16) __half g_wvTh[D_*D_], g_wvTl[D_*D_];
__device__ __align__(16) __half g_qh [(size_t)RQ_*D_], g_ql [(size_t)RQ_*D_];
__device__ __align__(16) __half g_kpvh[(size_t)R_*D_], g_kpvl[(size_t)R_*D_];
__device__ __align__(16) float  g_v[(size_t)R_*D_];
__device__ __align__(16) __half g_vth[(size_t)B_*D_*N_], g_vtl[(size_t)B_*D_*N_];
__device__ __align__(16) float  g_logits[(size_t)B_*M_*N_];   // 256 MB
__device__ __align__(16) float  g_cstat[B_*N_];
__device__ __align__(16) float  g_part[(size_t)B_*NSPLIT*M_*D_];

// ======================= small helpers ======================================
__device__ __forceinline__ uint32_t smem_u32(const void* p) {
    uint32_t a;
    asm("{ .reg .u64 t; cvta.to.shared.u64 t, %1; cvt.u32.u64 %0, t; }" : "=r"(a) : "l"(p));
    return a;
}
__device__ __forceinline__ void cp16(uint32_t dst, const void* src) {
    asm volatile("cp.async.cg.shared.global [%0], [%1], 16;" :: "r"(dst), "l"(src));
}
#define CP_COMMIT() asm volatile("cp.async.commit_group;" ::: "memory")
#define CP_WAIT0()  asm volatile("cp.async.wait_group 0;" ::: "memory")
#define CP_WAIT1()  asm volatile("cp.async.wait_group 1;" ::: "memory")

__device__ __forceinline__ void ldsm_x4(uint32_t& r0, uint32_t& r1, uint32_t& r2, uint32_t& r3,
                                        uint32_t addr) {
    asm volatile("ldmatrix.sync.aligned.m8n8.x4.shared.b16 {%0,%1,%2,%3}, [%4];"
                 : "=r"(r0), "=r"(r1), "=r"(r2), "=r"(r3) : "r"(addr));
}
__device__ __forceinline__ void mma16816(float* c, const uint32_t* a, uint32_t b0, uint32_t b1) {
    asm volatile(
        "mma.sync.aligned.m16n8k16.row.col.f32.f16.f16.f32 "
        "{%0,%1,%2,%3}, {%4,%5,%6,%7}, {%8,%9}, {%0,%1,%2,%3};"
        : "+f"(c[0]), "+f"(c[1]), "+f"(c[2]), "+f"(c[3])
        : "r"(a[0]), "r"(a[1]), "r"(a[2]), "r"(a[3]), "r"(b0), "r"(b1));
}

// swizzled byte offset in a 128-row x 32-half tile (64B rows)
__device__ __forceinline__ uint32_t sw(int row, int c16) {
    return (uint32_t)(row * 64 + ((c16 ^ ((row ^ (row >> 2)) & 3)) << 4));
}

// fast exp, FFMA-only (no MUFU). Valid for x <= 0 (args here are always <= 0).
__device__ __forceinline__ float fexp(float x) {
    x = fmaxf(x, -80.0f);
    float nf = fmaf(x, 1.4426950408889634f, 12582912.0f);
    int  i   = __float_as_int(nf) - 0x4B400000;
    float n  = nf - 12582912.0f;
    float f  = fmaf(n, -0.693145751953125f, x);
    f        = fmaf(n, -1.42860682030941723e-6f, f);
    float p = 1.3888889e-3f;
    p = fmaf(p, f, 8.3333333e-3f);
    p = fmaf(p, f, 4.1666668e-2f);
    p = fmaf(p, f, 1.6666667e-1f);
    p = fmaf(p, f, 5.0e-1f);
    p = fmaf(p, f, 1.0f);
    p = fmaf(p, f, 1.0f);
    return p * __int_as_float((i + 127) << 23);
}

// ======================= shared MMA stage compute ============================
// stage layout: Ah @ +0, Al @ +8192, Bh @ +16384, Bl @ +24576
__device__ __forceinline__ void compute_stage(uint32_t sb, int mw0, int nw0,
                                              float cacc[4][4][4], int lane) {
    int arow = lane & 15, asel = lane >> 4;
    int brow = (lane & 7) + ((lane >> 4) << 3), bsel = (lane >> 3) & 1;
#pragma unroll
    for (int ks = 0; ks < 2; ks++) {
        uint32_t ah[4][4], bh[2][4];
#pragma unroll
        for (int mi = 0; mi < 4; mi++)
            ldsm_x4(ah[mi][0], ah[mi][1], ah[mi][2], ah[mi][3],
                    sb + sw(mw0 + mi*16 + arow, ks*2 + asel));
#pragma unroll
        for (int nb = 0; nb < 2; nb++)
            ldsm_x4(bh[nb][0], bh[nb][1], bh[nb][2], bh[nb][3],
                    sb + 16384 + sw(nw0 + nb*16 + brow, ks*2 + bsel));
#pragma unroll
        for (int mi = 0; mi < 4; mi++)
#pragma unroll
            for (int nj = 0; nj < 4; nj++)
                mma16816(cacc[mi][nj], ah[mi], bh[nj>>1][(nj&1)*2], bh[nj>>1][(nj&1)*2+1]);

        uint32_t bl[2][4];
#pragma unroll
        for (int nb = 0; nb < 2; nb++)
            ldsm_x4(bl[nb][0], bl[nb][1], bl[nb][2], bl[nb][3],
                    sb + 24576 + sw(nw0 + nb*16 + brow, ks*2 + bsel));
#pragma unroll
        for (int mi = 0; mi < 4; mi++)
#pragma unroll
            for (int nj = 0; nj < 4; nj++)
                mma16816(cacc[mi][nj], ah[mi], bl[nj>>1][(nj&1)*2], bl[nj>>1][(nj&1)*2+1]);

        uint32_t al[4][4];
#pragma unroll
        for (int mi = 0; mi < 4; mi++)
            ldsm_x4(al[mi][0], al[mi][1], al[mi][2], al[mi][3],
                    sb + 8192 + sw(mw0 + mi*16 + arow, ks*2 + asel));
#pragma unroll
        for (int mi = 0; mi < 4; mi++)
#pragma unroll
            for (int nj = 0; nj < 4; nj++)
                mma16816(cacc[mi][nj], al[mi], bh[nj>>1][(nj&1)*2], bh[nj>>1][(nj&1)*2+1]);
    }
}

// cp.async staging of a full stage (A hi/lo + B hi/lo), 128x32 halves each
__device__ __forceinline__ void stage4(uint32_t sb,
                                       const __half* __restrict__ Ah, const __half* __restrict__ Al,
                                       size_t ar0, int lda,
                                       const __half* __restrict__ Bh, const __half* __restrict__ Bl,
                                       size_t br0, int ldb, int k0) {
    int t = threadIdx.x;
#pragma unroll
    for (int i = 0; i < 2; i++) {
        int c = t + 256*i;
        int row = c >> 2, c16 = c & 3;
        uint32_t so = sw(row, c16);
        size_t ka = (size_t)k0 + c16*8;
        cp16(sb + so,         Ah + (ar0 + row)*(size_t)lda + ka);
        cp16(sb + 8192 + so,  Al + (ar0 + row)*(size_t)lda + ka);
        cp16(sb + 16384 + so, Bh + (br0 + row)*(size_t)ldb + ka);
        cp16(sb + 24576 + so, Bl + (br0 + row)*(size_t)ldb + ka);
    }
}

// ======================= K0: positional path ================================
__global__ void pv_relu_kernel(const float* __restrict__ p_xyz, const float* __restrict__ v_xyz,
                               const float* __restrict__ Wp1, const float* __restrict__ bp1,
                               const float* __restrict__ ln_w, const float* __restrict__ ln_b) {
    int idx = blockIdx.x * blockDim.x + threadIdx.x;
    if (idx >= R_) return;
    int b = idx / N_;
    float d0 = fabsf(p_xyz[idx*3+0] - v_xyz[b*3+0]);
    float d1 = fabsf(p_xyz[idx*3+1] - v_xyz[b*3+1]);
    float d2 = fabsf(p_xyz[idx*3+2] - v_xyz[b*3+2]);
    float h0 = d0*Wp1[0] + d1*Wp1[3] + d2*Wp1[6] + bp1[0];
    float h1 = d0*Wp1[1] + d1*Wp1[4] + d2*Wp1[7] + bp1[1];
    float h2 = d0*Wp1[2] + d1*Wp1[5] + d2*Wp1[8] + bp1[2];
    float mu = (h0 + h1 + h2) * (1.0f/3.0f);
    float e0 = h0-mu, e1 = h1-mu, e2 = h2-mu;
    float inv = rsqrtf((e0*e0 + e1*e1 + e2*e2) * (1.0f/3.0f) + 1e-5f);
    g_r[idx*3+0] = fmaxf(e0*inv*ln_w[0] + ln_b[0], 0.0f);
    g_r[idx*3+1] = fmaxf(e1*inv*ln_w[1] + ln_b[1], 0.0f);
    g_r[idx*3+2] = fmaxf(e2*inv*ln_w[2] + ln_b[2], 0.0f);
}

// ======================= prep: hi/lo splits ==================================
__global__ void split_kernel(const float* __restrict__ src, __half* __restrict__ hi,
                             __half* __restrict__ lo, int n2) {
    int i = blockIdx.x * blockDim.x + threadIdx.x;
    if (i >= n2) return;
    float2 v = reinterpret_cast<const float2*>(src)[i];
    __half h0 = __float2half_rn(v.x), h1 = __float2half_rn(v.y);
    __half l0 = __float2half_rn(v.x - __half2float(h0));
    __half l1 = __float2half_rn(v.y - __half2float(h1));
    reinterpret_cast<__half2*>(hi)[i] = __halves2half2(h0, h1);
    reinterpret_cast<__half2*>(lo)[i] = __halves2half2(l0, l1);
}

__global__ void wtsplit_kernel(const float* __restrict__ W, __half* __restrict__ Th,
                               __half* __restrict__ Tl) {
    int i = blockIdx.x * blockDim.x + threadIdx.x;   // 65536
    int d = i >> 8, c = i & 255;
    float v = W[i];
    __half h = __float2half_rn(v);
    Th[c*256 + d] = h;
    Tl[c*256 + d] = __float2half_rn(v - __half2float(h));
}

__global__ void vtrans_kernel() {
    __shared__ float tl[32][33];
    int n0 = blockIdx.x * 32, d0 = blockIdx.y * 32, b = blockIdx.z;
    int tx = threadIdx.x, ty = threadIdx.y;
#pragma unroll
    for (int k = 0; k < 4; k++)
        tl[ty + k*8][tx] = g_v[(size_t)(b*N_ + n0 + ty + k*8)*D_ + d0 + tx];
    __syncthreads();
#pragma unroll
    for (int k = 0; k < 4; k++) {
        int d = d0 + ty + k*8;
        float v = tl[tx][ty + k*8];
        __half h = __float2half_rn(v);
        size_t o = (size_t)(b*D_ + d)*N_ + n0 + tx;
        g_vth[o] = h;
        g_vtl[o] = __float2half_rn(v - __half2float(h));
    }
}

// ======================= projections (HMMA) ==================================
// mode 0: q = vf@Wq + bq -> qh/ql ; 1: kpv = p@Wk + bk + pv -> kpvh/l ; 2: v (fp32)
__global__ __launch_bounds__(256)
void proj_mma_kernel(const __half* __restrict__ Xh, const __half* __restrict__ Xl,
                     const __half* __restrict__ WTh, const __half* __restrict__ WTl,
                     const float* __restrict__ bias, const float* __restrict__ Wp2,
                     const float* __restrict__ bp2, int mode) {
    extern __shared__ char dyn[];
    uint32_t sb = smem_u32(dyn);
    size_t row0 = (size_t)blockIdx.y * 128;
    int c0 = blockIdx.x * 128;
    int lane = threadIdx.x & 31, wid = threadIdx.x >> 5;
    int mw0 = (wid >> 2) * 64, nw0 = (wid & 3) * 32;
    float cacc[4][4][4] = {};

    stage4(sb, Xh, Xl, row0, D_, WTh, WTl, (size_t)c0, D_, 0); CP_COMMIT();
    for (int s = 0; s < 8; s++) {
        if (s + 1 < 8) { stage4(sb + ((s+1)&1)*STAGE_BYTES, Xh, Xl, row0, D_, WTh, WTl, (size_t)c0, D_, (s+1)*32); CP_COMMIT(); CP_WAIT1(); }
        else CP_WAIT0();
        __syncthreads();
        compute_stage(sb + (s&1)*STAGE_BYTES, mw0, nw0, cacc, lane);
        __syncthreads();
    }

    int g = lane >> 2, tg = lane & 3;
#pragma unroll
    for (int mi = 0; mi < 4; mi++) {
#pragma unroll
        for (int half_m = 0; half_m < 2; half_m++) {
            size_t r = row0 + mw0 + mi*16 + g + half_m*8;
            float q0 = 0.f, q1 = 0.f, q2 = 0.f;
            if (mode == 1) { q0 = g_r[r*3+0]; q1 = g_r[r*3+1]; q2 = g_r[r*3+2]; }
#pragma unroll
            for (int nj = 0; nj < 4; nj++) {
#pragma unroll
                for (int e = 0; e < 2; e++) {
                    int c = c0 + nw0 + nj*8 + tg*2 + e;
                    float v = cacc[mi][nj][half_m*2 + e] + bias[c];
                    if (mode == 1) v += q0*Wp2[c] + q1*Wp2[D_+c] + q2*Wp2[2*D_+c] + bp2[c];
                    if (mode == 2) { g_v[r*D_ + c] = v; }
                    else {
                        __half h = __float2half_rn(v);
                        __half l = __float2half_rn(v - __half2float(h));
                        if (mode == 0) { g_qh[r*D_+c] = h;   g_ql[r*D_+c] = l; }
                        else           { g_kpvh[r*D_+c] = h; g_kpvl[r*D_+c] = l; }
                    }
                }
            }
        }
    }
}

// ======================= logits (HMMA) =======================================
__global__ __launch_bounds__(256)
void logits_mma_kernel() {
    extern __shared__ char dyn[];
    uint32_t sb = smem_u32(dyn);
    int b = blockIdx.z;
    int n0 = blockIdx.x * 128, m0 = blockIdx.y * 128;
    size_t ar0 = (size_t)b*M_ + m0, br0 = (size_t)b*N_ + n0;
    int lane = threadIdx.x & 31, wid = threadIdx.x >> 5;
    int mw0 = (wid >> 2) * 64, nw0 = (wid & 3) * 32;
    float cacc[4][4][4] = {};

    stage4(sb, g_qh, g_ql, ar0, D_, g_kpvh, g_kpvl, br0, D_, 0); CP_COMMIT();
    for (int s = 0; s < 8; s++) {
        if (s + 1 < 8) { stage4(sb + ((s+1)&1)*STAGE_BYTES, g_qh, g_ql, ar0, D_, g_kpvh, g_kpvl, br0, D_, (s+1)*32); CP_COMMIT(); CP_WAIT1(); }
        else CP_WAIT0();
        __syncthreads();
        compute_stage(sb + (s&1)*STAGE_BYTES, mw0, nw0, cacc, lane);
        __syncthreads();
    }

    int g = lane >> 2, tg = lane & 3;
    float* L = g_logits + (size_t)b*M_*N_;
#pragma unroll
    for (int mi = 0; mi < 4; mi++)
#pragma unroll
        for (int nj = 0; nj < 4; nj++) {
            int m = m0 + mw0 + mi*16 + g;
            int n = n0 + nw0 + nj*8 + tg*2;
            float2 v0 = { cacc[mi][nj][0]*0.0625f, cacc[mi][nj][1]*0.0625f };
            float2 v1 = { cacc[mi][nj][2]*0.0625f, cacc[mi][nj][3]*0.0625f };
            *reinterpret_cast<float2*>(&L[(size_t)m*N_ + n])     = v0;
            *reinterpret_cast<float2*>(&L[(size_t)(m+8)*N_ + n]) = v1;
        }
}

// ======================= softmax stats over m (online) =======================
__global__ void col_stats_kernel() {
    __shared__ float red_m[8][33], red_s[8][33];
    int tx = threadIdx.x, ty = threadIdx.y;
    int col = blockIdx.x * 32 + tx;
    int b = col >> 14, n = col & (N_-1);
    const float* L = g_logits + (size_t)b*M_*N_ + n;
    float mx = -1e30f, sum = 0.0f;
    for (int m = ty; m < M_; m += 8) {
        float v = L[(size_t)m*N_];
        if (v > mx) { sum = sum * fexp(mx - v) + 1.0f; mx = v; }
        else        { sum += fexp(v - mx); }
    }
    red_m[ty][tx] = mx; red_s[ty][tx] = sum;
    __syncthreads();
    if (ty == 0) {
#pragma unroll
        for (int u = 1; u < 8; u++) {
            float m2 = red_m[u][tx], s2 = red_s[u][tx];
            if (m2 > mx) { sum = sum * fexp(mx - m2) + s2; mx = m2; }
            else         { sum += s2 * fexp(m2 - mx); }
        }
        g_cstat[col] = mx + __logf(sum);
    }
}

// ======================= weighted value (HMMA, split-K, fused exp) ===========
__global__ __launch_bounds__(256)
void wv_mma_kernel() {
    extern __shared__ char dyn[];
    uint32_t sb = smem_u32(dyn);
    int z = blockIdx.z, b = z >> 3, sp = z & 7;
    int d0 = blockIdx.x * 128, m0 = blockIdx.y * 128;
    int kbeg = sp * KR_;
    const float* L  = g_logits + (size_t)b*M_*N_;
    const float* CS = g_cstat + b*N_;
    size_t br0 = (size_t)b*D_ + d0;
    int t = threadIdx.x, lane = t & 31, wid = t >> 5;
    int mw0 = (wid >> 2) * 64, nw0 = (wid & 3) * 32;
    float cacc[4][4][4] = {};

    int rows[2], c16s[2];
#pragma unroll
    for (int i = 0; i < 2; i++) { int c = t + 256*i; rows[i] = c >> 2; c16s[i] = c & 3; }

    float4 ra[2][2];
    // prologue: LDG A(0), cp.async B(0)
#pragma unroll
    for (int i = 0; i < 2; i++) {
        size_t base = (size_t)(m0 + rows[i])*N_ + kbeg + c16s[i]*8;
        ra[i][0] = *reinterpret_cast<const float4*>(&L[base]);
        ra[i][1] = *reinterpret_cast<const float4*>(&L[base + 4]);
    }
#pragma unroll
    for (int i = 0; i < 2; i++) {
        uint32_t so = sw(rows[i], c16s[i]);
        size_t ka = (size_t)kbeg + c16s[i]*8;
        cp16(sb + 16384 + so, g_vth + (br0 + rows[i])*(size_t)N_ + ka);
        cp16(sb + 24576 + so, g_vtl + (br0 + rows[i])*(size_t)N_ + ka);
    }
    CP_COMMIT();

    const int NCH = KR_ / 32;   // 64
    for (int s = 0; s < NCH; s++) {
        uint32_t buf = sb + (s&1)*STAGE_BYTES;
        char*    bufp = dyn + (s&1)*STAGE_BYTES;
        CP_WAIT0();
        __syncthreads();
        // transform + STS A(s)
#pragma unroll
        for (int i = 0; i < 2; i++) {
            int kabs = kbeg + s*32 + c16s[i]*8;
            float4 cs0 = *reinterpret_cast<const float4*>(&CS[kabs]);
            float4 cs1 = *reinterpret_cast<const float4*>(&CS[kabs + 4]);
            float w[8];
            w[0] = fexp(ra[i][0].x - cs0.x); w[1] = fexp(ra[i][0].y - cs0.y);
            w[2] = fexp(ra[i][0].z - cs0.z); w[3] = fexp(ra[i][0].w - cs0.w);
            w[4] = fexp(ra[i][1].x - cs1.x); w[5] = fexp(ra[i][1].y - cs1.y);
            w[6] = fexp(ra[i][1].z - cs1.z); w[7] = fexp(ra[i][1].w - cs1.w);
            uint32_t hi[4], lo[4];
#pragma unroll
            for (int j = 0; j < 4; j++) {
                __half h0 = __float2half_rn(w[2*j]), h1 = __float2half_rn(w[2*j+1]);
                __half l0 = __float2half_rn(w[2*j]   - __half2float(h0));
                __half l1 = __float2half_rn(w[2*j+1] - __half2float(h1));
                hi[j] = (uint32_t)__half_as_ushort(h0) | ((uint32_t)__half_as_ushort(h1) << 16);
                lo[j] = (uint32_t)__half_as_ushort(l0) | ((uint32_t)__half_as_ushort(l1) << 16);
            }
            uint32_t so = sw(rows[i], c16s[i]);
            *reinterpret_cast<uint4*>(bufp + so)        = make_uint4(hi[0], hi[1], hi[2], hi[3]);
            *reinterpret_cast<uint4*>(bufp + 8192 + so) = make_uint4(lo[0], lo[1], lo[2], lo[3]);
        }
        if (s + 1 < NCH) {
            int kn = kbeg + (s+1)*32;
#pragma unroll
            for (int i = 0; i < 2; i++) {
                size_t base = (size_t)(m0 + rows[i])*N_ + kn + c16s[i]*8;
                ra[i][0] = *reinterpret_cast<const float4*>(&L[base]);
                ra[i][1] = *reinterpret_cast<const float4*>(&L[base + 4]);
            }
            uint32_t nbuf = sb + ((s+1)&1)*STAGE_BYTES;
#pragma unroll
            for (int i = 0; i < 2; i++) {
                uint32_t so = sw(rows[i], c16s[i]);
                size_t ka = (size_t)kn + c16s[i]*8;
                cp16(nbuf + 16384 + so, g_vth + (br0 + rows[i])*(size_t)N_ + ka);
                cp16(nbuf + 24576 + so, g_vtl + (br0 + rows[i])*(size_t)N_ + ka);
            }
            CP_COMMIT();
        }
        __syncthreads();
        compute_stage(buf, mw0, nw0, cacc, lane);
    }

    int g = lane >> 2, tg = lane & 3;
    float* P = g_part + (size_t)z*M_*D_;
#pragma unroll
    for (int mi = 0; mi < 4; mi++)
#pragma unroll
        for (int nj = 0; nj < 4; nj++) {
            int m = m0 + mw0 + mi*16 + g;
            int d = d0 + nw0 + nj*8 + tg*2;
            float2 v0 = { cacc[mi][nj][0], cacc[mi][nj][1] };
            float2 v1 = { cacc[mi][nj][2], cacc[mi][nj][3] };
            *reinterpret_cast<float2*>(&P[(size_t)m*D_ + d])     = v0;
            *reinterpret_cast<float2*>(&P[(size_t)(m+8)*D_ + d]) = v1;
        }
}

// ======================= reduce + residual ===================================
__global__ void reduce_kernel(const float* __restrict__ Vf, float* __restrict__ out) {
    int i4 = blockIdx.x * blockDim.x + threadIdx.x;   // RQ_*D_/4
    int row = i4 >> 6;
    int b = row >> 11;
    int mrow = row & (M_ - 1);
    int d4 = i4 & 63;
    float4 acc = reinterpret_cast<const float4*>(Vf)[i4];
#pragma unroll
    for (int s = 0; s < NSPLIT; s++) {
        size_t pi = ((size_t)(b*NSPLIT + s)*M_ + mrow)*64 + d4;
        float4 p = reinterpret_cast<const float4*>(g_part)[pi];
        acc.x += p.x; acc.y += p.y; acc.z += p.z; acc.w += p.w;
    }
    reinterpret_cast<float4*>(out)[i4] = acc;
}

// ======================= launcher ============================================
extern "C" void kernel_launch(void* const* d_in, const int* in_sizes, int n_in,
                              void* d_out, int out_size) {
    const float* p_xyz      = (const float*)d_in[0];
    const float* v_xyz      = (const float*)d_in[1];
    const float* p_features = (const float*)d_in[2];
    const float* v_features = (const float*)d_in[3];
    const float* Wq  = (const float*)d_in[4];
    const float* bq  = (const float*)d_in[5];
    const float* Wk  = (const float*)d_in[6];
    const float* bk  = (const float*)d_in[7];
    const float* Wv  = (const float*)d_in[8];
    const float* bv  = (const float*)d_in[9];
    const float* Wp1 = (const float*)d_in[10];
    const float* bp1 = (const float*)d_in[11];
    const float* ln_w = (const float*)d_in[12];
    const float* ln_b = (const float*)d_in[13];
    const float* Wp2 = (const float*)d_in[14];
    const float* bp2 = (const float*)d_in[15];
    float* out = (float*)d_out;

    static int attr_done = 0;
    if (!attr_done) {
        cudaFuncSetAttribute(proj_mma_kernel,   cudaFuncAttributeMaxDynamicSharedMemorySize, DYN_SMEM);
        cudaFuncSetAttribute(logits_mma_kernel, cudaFuncAttributeMaxDynamicSharedMemorySize, DYN_SMEM);
        cudaFuncSetAttribute(wv_mma_kernel,     cudaFuncAttributeMaxDynamicSharedMemorySize, DYN_SMEM);
        attr_done = 1;
    }

    __half *ph, *pl, *vfh, *vfl, *wqh, *wql, *wkh, *wkl, *wvh, *wvl;
    cudaGetSymbolAddress((void**)&ph,  g_ph);
    cudaGetSymbolAddress((void**)&pl,  g_pl);
    cudaGetSymbolAddress((void**)&vfh, g_vfh);
    cudaGetSymbolAddress((void**)&vfl, g_vfl);
    cudaGetSymbolAddress((void**)&wqh, g_wqTh);
    cudaGetSymbolAddress((void**)&wql, g_wqTl);
    cudaGetSymbolAddress((void**)&wkh, g_wkTh);
    cudaGetSymbolAddress((void**)&wkl, g_wkTl);
    cudaGetSymbolAddress((void**)&wvh, g_wvTh);
    cudaGetSymbolAddress((void**)&wvl, g_wvTl);

    split_kernel<<<((size_t)R_*D_/2 + 255)/256, 256>>>(p_features, ph, pl, R_*D_/2);
    split_kernel<<<((size_t)RQ_*D_/2 + 255)/256, 256>>>(v_features, vfh, vfl, RQ_*D_/2);
    wtsplit_kernel<<<256, 256>>>(Wq, wqh, wql);
    wtsplit_kernel<<<256, 256>>>(Wk, wkh, wkl);
    wtsplit_kernel<<<256, 256>>>(Wv, wvh, wvl);

    pv_relu_kernel<<<R_/256, 256>>>(p_xyz, v_xyz, Wp1, bp1, ln_w, ln_b);

    proj_mma_kernel<<<dim3(2, RQ_/128), 256, DYN_SMEM>>>(vfh, vfl, wqh, wql, bq, Wp2, bp2, 0);
    proj_mma_kernel<<<dim3(2, R_/128),  256, DYN_SMEM>>>(ph, pl, wkh, wkl, bk, Wp2, bp2, 1);
    proj_mma_kernel<<<dim3(2, R_/128),  256, DYN_SMEM>>>(ph, pl, wvh, wvl, bv, Wp2, bp2, 2);

    vtrans_kernel<<<dim3(N_/32, D_/32, B_), dim3(32, 8)>>>();

    logits_mma_kernel<<<dim3(N_/128, M_/128, B_), 256, DYN_SMEM>>>();

    col_stats_kernel<<<(B_*N_)/32, dim3(32, 8)>>>();

    wv_mma_kernel<<<dim3(D_/128, M_/128, B_*NSPLIT), 256, DYN_SMEM>>>();
    reduce_kernel<<<(RQ_*D_/4)/256, 256>>>(v_features, out);
}

// round 5
// speedup vs baseline: 3.4371x; 1.2693x over previous
#include <cuda_runtime.h>
#include <cuda_fp16.h>
#include <stdint.h>
#include <math.h>

#define B_  2
#define N_  16384
#define M_  2048
#define D_  256
#define R_  (B_*N_)
#define RQ_ (B_*M_)
#define NSPLIT 8
#define KR_ (N_/NSPLIT)          // 2048 contraction per wv split
#define NMT 16                   // number of m-tiles (M_/128)
#define STAGE_BYTES 32768        // logits/proj: Ah(8K) Al(8K) Bh(8K) Bl(8K)
#define DYN_SMEM (2*STAGE_BYTES)
#define STAGE_WV 24576           // wv: Ah(8K) Bh(8K) Bl(8K)
#define DYN_SMEM_WV (2*STAGE_WV)

// ======================= device scratch =====================================
__device__ __align__(16) float  g_r[R_*3];
__device__ __align__(16) __half g_ph [(size_t)R_*D_],  g_pl [(size_t)R_*D_];
__device__ __align__(16) __half g_vfh[(size_t)RQ_*D_], g_vfl[(size_t)RQ_*D_];
__device__ __align__(16) __half g_wqTh[D_*D_], g_wqTl[D_*D_];
__device__ __align__(16) __half g_wkTh[D_*D_], g_wkTl[D_*D_];
__device__ __align__(16) __half g_wvTh[D_*D_], g_wvTl[D_*D_];
__device__ __align__(16) __half g_qh [(size_t)RQ_*D_], g_ql [(size_t)RQ_*D_];
__device__ __align__(16) __half g_kpvh[(size_t)R_*D_], g_kpvl[(size_t)R_*D_];
__device__ __align__(16) float  g_v[(size_t)R_*D_];
__device__ __align__(16) __half g_vth[(size_t)B_*D_*N_], g_vtl[(size_t)B_*D_*N_];
__device__ __align__(16) float  g_logits[(size_t)B_*M_*N_];   // 256 MB (scaled)
__device__ __align__(16) float  g_pmax[NMT*B_*N_], g_psum[NMT*B_*N_];
__device__ __align__(16) float  g_cstat[B_*N_];
__device__ __align__(16) float  g_part[(size_t)B_*NSPLIT*M_*D_];

// ======================= small helpers ======================================
__device__ __forceinline__ uint32_t smem_u32(const void* p) {
    uint32_t a;
    asm("{ .reg .u64 t; cvta.to.shared.u64 t, %1; cvt.u32.u64 %0, t; }" : "=r"(a) : "l"(p));
    return a;
}
__device__ __forceinline__ void cp16(uint32_t dst, const void* src) {
    asm volatile("cp.async.cg.shared.global [%0], [%1], 16;" :: "r"(dst), "l"(src));
}
#define CP_COMMIT() asm volatile("cp.async.commit_group;" ::: "memory")
#define CP_WAIT0()  asm volatile("cp.async.wait_group 0;" ::: "memory")
#define CP_WAIT1()  asm volatile("cp.async.wait_group 1;" ::: "memory")

__device__ __forceinline__ void ldsm_x4(uint32_t& r0, uint32_t& r1, uint32_t& r2, uint32_t& r3,
                                        uint32_t addr) {
    asm volatile("ldmatrix.sync.aligned.m8n8.x4.shared.b16 {%0,%1,%2,%3}, [%4];"
                 : "=r"(r0), "=r"(r1), "=r"(r2), "=r"(r3) : "r"(addr));
}
__device__ __forceinline__ void mma16816(float* c, const uint32_t* a, uint32_t b0, uint32_t b1) {
    asm volatile(
        "mma.sync.aligned.m16n8k16.row.col.f32.f16.f16.f32 "
        "{%0,%1,%2,%3}, {%4,%5,%6,%7}, {%8,%9}, {%0,%1,%2,%3};"
        : "+f"(c[0]), "+f"(c[1]), "+f"(c[2]), "+f"(c[3])
        : "r"(a[0]), "r"(a[1]), "r"(a[2]), "r"(a[3]), "r"(b0), "r"(b1));
}

// swizzled byte offset in a 128-row x 32-half tile (64B rows)
__device__ __forceinline__ uint32_t sw(int row, int c16) {
    return (uint32_t)(row * 64 + ((c16 ^ ((row ^ (row >> 2)) & 3)) << 4));
}

// fast exp, FFMA-only (no MUFU). Valid for x <= 0 (args here are always <= 0).
__device__ __forceinline__ float fexp(float x) {
    x = fmaxf(x, -80.0f);
    float nf = fmaf(x, 1.4426950408889634f, 12582912.0f);
    int  i   = __float_as_int(nf) - 0x4B400000;
    float n  = nf - 12582912.0f;
    float f  = fmaf(n, -0.693145751953125f, x);
    f        = fmaf(n, -1.42860682030941723e-6f, f);
    float p = 1.3888889e-3f;
    p = fmaf(p, f, 8.3333333e-3f);
    p = fmaf(p, f, 4.1666668e-2f);
    p = fmaf(p, f, 1.6666667e-1f);
    p = fmaf(p, f, 5.0e-1f);
    p = fmaf(p, f, 1.0f);
    p = fmaf(p, f, 1.0f);
    return p * __int_as_float((i + 127) << 23);
}

// ======================= 3-pass MMA stage compute ============================
// stage layout: Ah @ +0, Al @ +8192, Bh @ +16384, Bl @ +24576
__device__ __forceinline__ void compute_stage(uint32_t sb, int mw0, int nw0,
                                              float cacc[4][4][4], int lane) {
    int arow = lane & 15, asel = lane >> 4;
    int brow = (lane & 7) + ((lane >> 4) << 3), bsel = (lane >> 3) & 1;
#pragma unroll
    for (int ks = 0; ks < 2; ks++) {
        uint32_t ah[4][4], bh[2][4];
#pragma unroll
        for (int mi = 0; mi < 4; mi++)
            ldsm_x4(ah[mi][0], ah[mi][1], ah[mi][2], ah[mi][3],
                    sb + sw(mw0 + mi*16 + arow, ks*2 + asel));
#pragma unroll
        for (int nb = 0; nb < 2; nb++)
            ldsm_x4(bh[nb][0], bh[nb][1], bh[nb][2], bh[nb][3],
                    sb + 16384 + sw(nw0 + nb*16 + brow, ks*2 + bsel));
#pragma unroll
        for (int mi = 0; mi < 4; mi++)
#pragma unroll
            for (int nj = 0; nj < 4; nj++)
                mma16816(cacc[mi][nj], ah[mi], bh[nj>>1][(nj&1)*2], bh[nj>>1][(nj&1)*2+1]);

        uint32_t bl[2][4];
#pragma unroll
        for (int nb = 0; nb < 2; nb++)
            ldsm_x4(bl[nb][0], bl[nb][1], bl[nb][2], bl[nb][3],
                    sb + 24576 + sw(nw0 + nb*16 + brow, ks*2 + bsel));
#pragma unroll
        for (int mi = 0; mi < 4; mi++)
#pragma unroll
            for (int nj = 0; nj < 4; nj++)
                mma16816(cacc[mi][nj], ah[mi], bl[nj>>1][(nj&1)*2], bl[nj>>1][(nj&1)*2+1]);

        uint32_t al[4][4];
#pragma unroll
        for (int mi = 0; mi < 4; mi++)
            ldsm_x4(al[mi][0], al[mi][1], al[mi][2], al[mi][3],
                    sb + 8192 + sw(mw0 + mi*16 + arow, ks*2 + asel));
#pragma unroll
        for (int mi = 0; mi < 4; mi++)
#pragma unroll
            for (int nj = 0; nj < 4; nj++)
                mma16816(cacc[mi][nj], al[mi], bh[nj>>1][(nj&1)*2], bh[nj>>1][(nj&1)*2+1]);
    }
}

// ======================= 2-pass MMA stage (wv): Ah@0, Bh@8192, Bl@16384 ======
__device__ __forceinline__ void compute_stage_wv(uint32_t sb, int mw0, int nw0,
                                                 float cacc[4][4][4], int lane) {
    int arow = lane & 15, asel = lane >> 4;
    int brow = (lane & 7) + ((lane >> 4) << 3), bsel = (lane >> 3) & 1;
#pragma unroll
    for (int ks = 0; ks < 2; ks++) {
        uint32_t ah[4][4], bh[2][4], bl[2][4];
#pragma unroll
        for (int mi = 0; mi < 4; mi++)
            ldsm_x4(ah[mi][0], ah[mi][1], ah[mi][2], ah[mi][3],
                    sb + sw(mw0 + mi*16 + arow, ks*2 + asel));
#pragma unroll
        for (int nb = 0; nb < 2; nb++)
            ldsm_x4(bh[nb][0], bh[nb][1], bh[nb][2], bh[nb][3],
                    sb + 8192 + sw(nw0 + nb*16 + brow, ks*2 + bsel));
#pragma unroll
        for (int mi = 0; mi < 4; mi++)
#pragma unroll
            for (int nj = 0; nj < 4; nj++)
                mma16816(cacc[mi][nj], ah[mi], bh[nj>>1][(nj&1)*2], bh[nj>>1][(nj&1)*2+1]);
#pragma unroll
        for (int nb = 0; nb < 2; nb++)
            ldsm_x4(bl[nb][0], bl[nb][1], bl[nb][2], bl[nb][3],
                    sb + 16384 + sw(nw0 + nb*16 + brow, ks*2 + bsel));
#pragma unroll
        for (int mi = 0; mi < 4; mi++)
#pragma unroll
            for (int nj = 0; nj < 4; nj++)
                mma16816(cacc[mi][nj], ah[mi], bl[nj>>1][(nj&1)*2], bl[nj>>1][(nj&1)*2+1]);
    }
}

// cp.async staging of a full 3-pass stage (A hi/lo + B hi/lo)
__device__ __forceinline__ void stage4(uint32_t sb,
                                       const __half* __restrict__ Ah, const __half* __restrict__ Al,
                                       size_t ar0, int lda,
                                       const __half* __restrict__ Bh, const __half* __restrict__ Bl,
                                       size_t br0, int ldb, int k0) {
    int t = threadIdx.x;
#pragma unroll
    for (int i = 0; i < 2; i++) {
        int c = t + 256*i;
        int row = c >> 2, c16 = c & 3;
        uint32_t so = sw(row, c16);
        size_t ka = (size_t)k0 + c16*8;
        cp16(sb + so,         Ah + (ar0 + row)*(size_t)lda + ka);
        cp16(sb + 8192 + so,  Al + (ar0 + row)*(size_t)lda + ka);
        cp16(sb + 16384 + so, Bh + (br0 + row)*(size_t)ldb + ka);
        cp16(sb + 24576 + so, Bl + (br0 + row)*(size_t)ldb + ka);
    }
}

// ======================= K0: positional path ================================
__global__ void pv_relu_kernel(const float* __restrict__ p_xyz, const float* __restrict__ v_xyz,
                               const float* __restrict__ Wp1, const float* __restrict__ bp1,
                               const float* __restrict__ ln_w, const float* __restrict__ ln_b) {
    int idx = blockIdx.x * blockDim.x + threadIdx.x;
    if (idx >= R_) return;
    int b = idx / N_;
    float d0 = fabsf(p_xyz[idx*3+0] - v_xyz[b*3+0]);
    float d1 = fabsf(p_xyz[idx*3+1] - v_xyz[b*3+1]);
    float d2 = fabsf(p_xyz[idx*3+2] - v_xyz[b*3+2]);
    float h0 = d0*Wp1[0] + d1*Wp1[3] + d2*Wp1[6] + bp1[0];
    float h1 = d0*Wp1[1] + d1*Wp1[4] + d2*Wp1[7] + bp1[1];
    float h2 = d0*Wp1[2] + d1*Wp1[5] + d2*Wp1[8] + bp1[2];
    float mu = (h0 + h1 + h2) * (1.0f/3.0f);
    float e0 = h0-mu, e1 = h1-mu, e2 = h2-mu;
    float inv = rsqrtf((e0*e0 + e1*e1 + e2*e2) * (1.0f/3.0f) + 1e-5f);
    g_r[idx*3+0] = fmaxf(e0*inv*ln_w[0] + ln_b[0], 0.0f);
    g_r[idx*3+1] = fmaxf(e1*inv*ln_w[1] + ln_b[1], 0.0f);
    g_r[idx*3+2] = fmaxf(e2*inv*ln_w[2] + ln_b[2], 0.0f);
}

// ======================= prep: all hi/lo splits (one launch) =================
#define NP2 ((size_t)R_*D_/2)
#define NV2 ((size_t)RQ_*D_/2)
__global__ void splitall_kernel(const float* __restrict__ P, const float* __restrict__ VF) {
    size_t i = (size_t)blockIdx.x * blockDim.x + threadIdx.x;
    const float* src; __half *hi, *lo; size_t j;
    if (i < NP2)                 { src = P;  hi = g_ph;  lo = g_pl;  j = i; }
    else if (i < NP2 + NV2)      { src = VF; hi = g_vfh; lo = g_vfl; j = i - NP2; }
    else return;
    float2 v = reinterpret_cast<const float2*>(src)[j];
    __half h0 = __float2half_rn(v.x), h1 = __float2half_rn(v.y);
    __half l0 = __float2half_rn(v.x - __half2float(h0));
    __half l1 = __float2half_rn(v.y - __half2float(h1));
    reinterpret_cast<__half2*>(hi)[j] = __halves2half2(h0, h1);
    reinterpret_cast<__half2*>(lo)[j] = __halves2half2(l0, l1);
}

__global__ void wtsplitall_kernel(const float* __restrict__ Wq, const float* __restrict__ Wk,
                                  const float* __restrict__ Wv) {
    int i = blockIdx.x * blockDim.x + threadIdx.x;   // 3*65536
    int w = i >> 16, rem = i & 65535;
    int d = rem >> 8, c = rem & 255;
    const float* W = (w == 0) ? Wq : (w == 1) ? Wk : Wv;
    __half* Th = (w == 0) ? g_wqTh : (w == 1) ? g_wkTh : g_wvTh;
    __half* Tl = (w == 0) ? g_wqTl : (w == 1) ? g_wkTl : g_wvTl;
    float v = W[rem];
    __half h = __float2half_rn(v);
    Th[c*256 + d] = h;
    Tl[c*256 + d] = __float2half_rn(v - __half2float(h));
}

// ======================= fused projections (HMMA, one launch) ================
// z=0: q = vf@Wq + bq -> qh/ql ; z=1: kpv = p@Wk + bk + pv ; z=2: v (fp32)
__global__ __launch_bounds__(256)
void proj_mma_kernel(const float* __restrict__ bq, const float* __restrict__ bk,
                     const float* __restrict__ bv, const float* __restrict__ Wp2,
                     const float* __restrict__ bp2) {
    int mode = blockIdx.z;
    if (mode == 0 && blockIdx.y >= RQ_/128) return;
    extern __shared__ char dyn[];
    uint32_t sb = smem_u32(dyn);
    const __half *Xh, *Xl, *WTh, *WTl; const float* bias;
    if (mode == 0)      { Xh = g_vfh; Xl = g_vfl; WTh = g_wqTh; WTl = g_wqTl; bias = bq; }
    else if (mode == 1) { Xh = g_ph;  Xl = g_pl;  WTh = g_wkTh; WTl = g_wkTl; bias = bk; }
    else                { Xh = g_ph;  Xl = g_pl;  WTh = g_wvTh; WTl = g_wvTl; bias = bv; }

    size_t row0 = (size_t)blockIdx.y * 128;
    int c0 = blockIdx.x * 128;
    int lane = threadIdx.x & 31, wid = threadIdx.x >> 5;
    int mw0 = (wid >> 2) * 64, nw0 = (wid & 3) * 32;
    float cacc[4][4][4] = {};

    stage4(sb, Xh, Xl, row0, D_, WTh, WTl, (size_t)c0, D_, 0); CP_COMMIT();
    for (int s = 0; s < 8; s++) {
        if (s + 1 < 8) { stage4(sb + ((s+1)&1)*STAGE_BYTES, Xh, Xl, row0, D_, WTh, WTl, (size_t)c0, D_, (s+1)*32); CP_COMMIT(); CP_WAIT1(); }
        else CP_WAIT0();
        __syncthreads();
        compute_stage(sb + (s&1)*STAGE_BYTES, mw0, nw0, cacc, lane);
        __syncthreads();
    }

    int g = lane >> 2, tg = lane & 3;
#pragma unroll
    for (int mi = 0; mi < 4; mi++) {
#pragma unroll
        for (int half_m = 0; half_m < 2; half_m++) {
            size_t r = row0 + mw0 + mi*16 + g + half_m*8;
            float q0 = 0.f, q1 = 0.f, q2 = 0.f;
            if (mode == 1) { q0 = g_r[r*3+0]; q1 = g_r[r*3+1]; q2 = g_r[r*3+2]; }
#pragma unroll
            for (int nj = 0; nj < 4; nj++) {
#pragma unroll
                for (int e = 0; e < 2; e++) {
                    int c = c0 + nw0 + nj*8 + tg*2 + e;
                    float v = cacc[mi][nj][half_m*2 + e] + bias[c];
                    if (mode == 1) v += q0*Wp2[c] + q1*Wp2[D_+c] + q2*Wp2[2*D_+c] + bp2[c];
                    if (mode == 2) { g_v[r*D_ + c] = v; }
                    else {
                        __half h = __float2half_rn(v);
                        __half l = __float2half_rn(v - __half2float(h));
                        if (mode == 0) { g_qh[r*D_+c] = h;   g_ql[r*D_+c] = l; }
                        else           { g_kpvh[r*D_+c] = h; g_kpvl[r*D_+c] = l; }
                    }
                }
            }
        }
    }
}

// ======================= V transpose + split =================================
__global__ void vtrans_kernel() {
    __shared__ float tl[32][33];
    int n0 = blockIdx.x * 32, d0 = blockIdx.y * 32, b = blockIdx.z;
    int tx = threadIdx.x, ty = threadIdx.y;
#pragma unroll
    for (int k = 0; k < 4; k++)
        tl[ty + k*8][tx] = g_v[(size_t)(b*N_ + n0 + ty + k*8)*D_ + d0 + tx];
    __syncthreads();
#pragma unroll
    for (int k = 0; k < 4; k++) {
        int d = d0 + ty + k*8;
        float v = tl[tx][ty + k*8];
        __half h = __float2half_rn(v);
        size_t o = (size_t)(b*D_ + d)*N_ + n0 + tx;
        g_vth[o] = h;
        g_vtl[o] = __float2half_rn(v - __half2float(h));
    }
}

// ======================= logits (HMMA) + fused partial softmax stats =========
__global__ __launch_bounds__(256)
void logits_mma_kernel() {
    extern __shared__ char dyn[];
    uint32_t sb = smem_u32(dyn);
    int b = blockIdx.z;
    int n0 = blockIdx.x * 128, m0 = blockIdx.y * 128;
    size_t ar0 = (size_t)b*M_ + m0, br0 = (size_t)b*N_ + n0;
    int lane = threadIdx.x & 31, wid = threadIdx.x >> 5;
    int mw0 = (wid >> 2) * 64, nw0 = (wid & 3) * 32;
    float cacc[4][4][4] = {};

    stage4(sb, g_qh, g_ql, ar0, D_, g_kpvh, g_kpvl, br0, D_, 0); CP_COMMIT();
    for (int s = 0; s < 8; s++) {
        if (s + 1 < 8) { stage4(sb + ((s+1)&1)*STAGE_BYTES, g_qh, g_ql, ar0, D_, g_kpvh, g_kpvl, br0, D_, (s+1)*32); CP_COMMIT(); CP_WAIT1(); }
        else CP_WAIT0();
        __syncthreads();
        compute_stage(sb + (s&1)*STAGE_BYTES, mw0, nw0, cacc, lane);
        __syncthreads();
    }

    // scale accumulators (logits are stored pre-scaled)
#pragma unroll
    for (int mi = 0; mi < 4; mi++)
#pragma unroll
        for (int nj = 0; nj < 4; nj++)
#pragma unroll
            for (int e = 0; e < 4; e++) cacc[mi][nj][e] *= 0.0625f;

    int g = lane >> 2, tg = lane & 3;
    float* L = g_logits + (size_t)b*M_*N_;
#pragma unroll
    for (int mi = 0; mi < 4; mi++)
#pragma unroll
        for (int nj = 0; nj < 4; nj++) {
            int m = m0 + mw0 + mi*16 + g;
            int n = n0 + nw0 + nj*8 + tg*2;
            float2 v0 = { cacc[mi][nj][0], cacc[mi][nj][1] };
            float2 v1 = { cacc[mi][nj][2], cacc[mi][nj][3] };
            *reinterpret_cast<float2*>(&L[(size_t)m*N_ + n])     = v0;
            *reinterpret_cast<float2*>(&L[(size_t)(m+8)*N_ + n]) = v1;
        }

    // per-column (over 128 m rows of this tile) max + sumexp partials
    __syncthreads();              // smem (dyn) free for reuse now
    float* smax = reinterpret_cast<float*>(dyn);        // [2][128]
    float* ssum = smax + 256;                            // [2][128]
#pragma unroll
    for (int nj = 0; nj < 4; nj++) {
#pragma unroll
        for (int ec = 0; ec < 2; ec++) {
            float mx = -1e30f;
#pragma unroll
            for (int mi = 0; mi < 4; mi++) {
                mx = fmaxf(mx, cacc[mi][nj][ec]);
                mx = fmaxf(mx, cacc[mi][nj][2 + ec]);
            }
            mx = fmaxf(mx, __shfl_xor_sync(0xFFFFFFFFu, mx, 4));
            mx = fmaxf(mx, __shfl_xor_sync(0xFFFFFFFFu, mx, 8));
            mx = fmaxf(mx, __shfl_xor_sync(0xFFFFFFFFu, mx, 16));
            float s = 0.0f;
#pragma unroll
            for (int mi = 0; mi < 4; mi++) {
                s += fexp(cacc[mi][nj][ec]     - mx);
                s += fexp(cacc[mi][nj][2 + ec] - mx);
            }
            s += __shfl_xor_sync(0xFFFFFFFFu, s, 4);
            s += __shfl_xor_sync(0xFFFFFFFFu, s, 8);
            s += __shfl_xor_sync(0xFFFFFFFFu, s, 16);
            if (g == 0) {
                int nc = (wid & 3)*32 + nj*8 + tg*2 + ec;
                smax[(wid >> 2)*128 + nc] = mx;
                ssum[(wid >> 2)*128 + nc] = s;
            }
        }
    }
    __syncthreads();
    int t = threadIdx.x;
    if (t < 128) {
        float m0v = smax[t], m1v = smax[128 + t];
        float s0  = ssum[t], s1  = ssum[128 + t];
        float mm = fmaxf(m0v, m1v);
        float ss = s0 * fexp(m0v - mm) + s1 * fexp(m1v - mm);
        int col = b*N_ + n0 + t;
        g_pmax[blockIdx.y*(B_*N_) + col] = mm;
        g_psum[blockIdx.y*(B_*N_) + col] = ss;
    }
}

// ======================= stats reduce over m-tiles ===========================
__global__ void cstat_reduce_kernel() {
    int col = blockIdx.x * blockDim.x + threadIdx.x;   // 0..B*N-1
    float mx = -1e30f, sum = 0.0f;
#pragma unroll
    for (int ti = 0; ti < NMT; ti++) {
        float m2 = g_pmax[ti*(B_*N_) + col];
        float s2 = g_psum[ti*(B_*N_) + col];
        if (m2 > mx) { sum = sum * fexp(mx - m2) + s2; mx = m2; }
        else         { sum += s2 * fexp(m2 - mx); }
    }
    g_cstat[col] = mx + __logf(sum);
}

// ======================= weighted value (HMMA 2-pass, split-K, fused exp) ====
__global__ __launch_bounds__(256)
void wv_mma_kernel() {
    extern __shared__ char dyn[];
    uint32_t sb = smem_u32(dyn);
    int z = blockIdx.z, b = z >> 3, sp = z & 7;
    int d0 = blockIdx.x * 128, m0 = blockIdx.y * 128;
    int kbeg = sp * KR_;
    const float* L  = g_logits + (size_t)b*M_*N_;
    const float* CS = g_cstat + b*N_;
    size_t br0 = (size_t)b*D_ + d0;
    int t = threadIdx.x, lane = t & 31, wid = t >> 5;
    int mw0 = (wid >> 2) * 64, nw0 = (wid & 3) * 32;
    float cacc[4][4][4] = {};

    int rows[2], c16s[2];
#pragma unroll
    for (int i = 0; i < 2; i++) { int c = t + 256*i; rows[i] = c >> 2; c16s[i] = c & 3; }

    float4 ra[2][2];
#pragma unroll
    for (int i = 0; i < 2; i++) {
        size_t base = (size_t)(m0 + rows[i])*N_ + kbeg + c16s[i]*8;
        ra[i][0] = *reinterpret_cast<const float4*>(&L[base]);
        ra[i][1] = *reinterpret_cast<const float4*>(&L[base + 4]);
    }
#pragma unroll
    for (int i = 0; i < 2; i++) {
        uint32_t so = sw(rows[i], c16s[i]);
        size_t ka = (size_t)kbeg + c16s[i]*8;
        cp16(sb + 8192  + so, g_vth + (br0 + rows[i])*(size_t)N_ + ka);
        cp16(sb + 16384 + so, g_vtl + (br0 + rows[i])*(size_t)N_ + ka);
    }
    CP_COMMIT();

    const int NCH = KR_ / 32;   // 64
    for (int s = 0; s < NCH; s++) {
        uint32_t buf = sb + (s&1)*STAGE_WV;
        char*    bufp = dyn + (s&1)*STAGE_WV;
        CP_WAIT0();
        __syncthreads();
        // transform + STS A(s): weights hi only (2-pass drops w_lo)
#pragma unroll
        for (int i = 0; i < 2; i++) {
            int kabs = kbeg + s*32 + c16s[i]*8;
            float4 cs0 = *reinterpret_cast<const float4*>(&CS[kabs]);
            float4 cs1 = *reinterpret_cast<const float4*>(&CS[kabs + 4]);
            float w[8];
            w[0] = fexp(ra[i][0].x - cs0.x); w[1] = fexp(ra[i][0].y - cs0.y);
            w[2] = fexp(ra[i][0].z - cs0.z); w[3] = fexp(ra[i][0].w - cs0.w);
            w[4] = fexp(ra[i][1].x - cs1.x); w[5] = fexp(ra[i][1].y - cs1.y);
            w[6] = fexp(ra[i][1].z - cs1.z); w[7] = fexp(ra[i][1].w - cs1.w);
            uint32_t hi[4];
#pragma unroll
            for (int j = 0; j < 4; j++) {
                __half h0 = __float2half_rn(w[2*j]), h1 = __float2half_rn(w[2*j+1]);
                hi[j] = (uint32_t)__half_as_ushort(h0) | ((uint32_t)__half_as_ushort(h1) << 16);
            }
            uint32_t so = sw(rows[i], c16s[i]);
            *reinterpret_cast<uint4*>(bufp + so) = make_uint4(hi[0], hi[1], hi[2], hi[3]);
        }
        if (s + 1 < NCH) {
            int kn = kbeg + (s+1)*32;
#pragma unroll
            for (int i = 0; i < 2; i++) {
                size_t base = (size_t)(m0 + rows[i])*N_ + kn + c16s[i]*8;
                ra[i][0] = *reinterpret_cast<const float4*>(&L[base]);
                ra[i][1] = *reinterpret_cast<const float4*>(&L[base + 4]);
            }
            uint32_t nbuf = sb + ((s+1)&1)*STAGE_WV;
#pragma unroll
            for (int i = 0; i < 2; i++) {
                uint32_t so = sw(rows[i], c16s[i]);
                size_t ka = (size_t)kn + c16s[i]*8;
                cp16(nbuf + 8192  + so, g_vth + (br0 + rows[i])*(size_t)N_ + ka);
                cp16(nbuf + 16384 + so, g_vtl + (br0 + rows[i])*(size_t)N_ + ka);
            }
            CP_COMMIT();
        }
        __syncthreads();
        compute_stage_wv(buf, mw0, nw0, cacc, lane);
    }

    int g = lane >> 2, tg = lane & 3;
    float* P = g_part + (size_t)z*M_*D_;
#pragma unroll
    for (int mi = 0; mi < 4; mi++)
#pragma unroll
        for (int nj = 0; nj < 4; nj++) {
            int m = m0 + mw0 + mi*16 + g;
            int d = d0 + nw0 + nj*8 + tg*2;
            float2 v0 = { cacc[mi][nj][0], cacc[mi][nj][1] };
            float2 v1 = { cacc[mi][nj][2], cacc[mi][nj][3] };
            *reinterpret_cast<float2*>(&P[(size_t)m*D_ + d])     = v0;
            *reinterpret_cast<float2*>(&P[(size_t)(m+8)*D_ + d]) = v1;
        }
}

// ======================= reduce + residual ===================================
__global__ void reduce_kernel(const float* __restrict__ Vf, float* __restrict__ out) {
    int i4 = blockIdx.x * blockDim.x + threadIdx.x;   // RQ_*D_/4
    int row = i4 >> 6;
    int b = row >> 11;
    int mrow = row & (M_ - 1);
    int d4 = i4 & 63;
    float4 acc = reinterpret_cast<const float4*>(Vf)[i4];
#pragma unroll
    for (int s = 0; s < NSPLIT; s++) {
        size_t pi = ((size_t)(b*NSPLIT + s)*M_ + mrow)*64 + d4;
        float4 p = reinterpret_cast<const float4*>(g_part)[pi];
        acc.x += p.x; acc.y += p.y; acc.z += p.z; acc.w += p.w;
    }
    reinterpret_cast<float4*>(out)[i4] = acc;
}

// ======================= launcher ============================================
extern "C" void kernel_launch(void* const* d_in, const int* in_sizes, int n_in,
                              void* d_out, int out_size) {
    const float* p_xyz      = (const float*)d_in[0];
    const float* v_xyz      = (const float*)d_in[1];
    const float* p_features = (const float*)d_in[2];
    const float* v_features = (const float*)d_in[3];
    const float* Wq  = (const float*)d_in[4];
    const float* bq  = (const float*)d_in[5];
    const float* Wk  = (const float*)d_in[6];
    const float* bk  = (const float*)d_in[7];
    const float* Wv  = (const float*)d_in[8];
    const float* bv  = (const float*)d_in[9];
    const float* Wp1 = (const float*)d_in[10];
    const float* bp1 = (const float*)d_in[11];
    const float* ln_w = (const float*)d_in[12];
    const float* ln_b = (const float*)d_in[13];
    const float* Wp2 = (const float*)d_in[14];
    const float* bp2 = (const float*)d_in[15];
    float* out = (float*)d_out;

    static int attr_done = 0;
    if (!attr_done) {
        cudaFuncSetAttribute(proj_mma_kernel,   cudaFuncAttributeMaxDynamicSharedMemorySize, DYN_SMEM);
        cudaFuncSetAttribute(logits_mma_kernel, cudaFuncAttributeMaxDynamicSharedMemorySize, DYN_SMEM);
        cudaFuncSetAttribute(wv_mma_kernel,     cudaFuncAttributeMaxDynamicSharedMemorySize, DYN_SMEM_WV);
        attr_done = 1;
    }

    // [0] input hi/lo splits (p_features + v_features, one launch)
    splitall_kernel<<<(unsigned)((NP2 + NV2 + 255)/256), 256>>>(p_features, v_features);
    // [1] weight transpose+split (all three, one launch)
    wtsplitall_kernel<<<768, 256>>>(Wq, Wk, Wv);
    // [2] positional path
    pv_relu_kernel<<<R_/256, 256>>>(p_xyz, v_xyz, Wp1, bp1, ln_w, ln_b);
    // [3] fused projections q/k/v
    proj_mma_kernel<<<dim3(2, R_/128, 3), 256, DYN_SMEM>>>(bq, bk, bv, Wp2, bp2);
    // [4] V transpose + split
    vtrans_kernel<<<dim3(N_/32, D_/32, B_), dim3(32, 8)>>>();
    // [5] logits + fused partial stats   <-- ncu -s 5 -c 1 lands here
    logits_mma_kernel<<<dim3(N_/128, M_/128, B_), 256, DYN_SMEM>>>();
    // [6] stats reduce
    cstat_reduce_kernel<<<(B_*N_)/256, 256>>>();
    // [7] weighted value (2-pass, split-K)
    wv_mma_kernel<<<dim3(D_/128, M_/128, B_*NSPLIT), 256, DYN_SMEM_WV>>>();
    // [8] reduce + residual
    reduce_kernel<<<(RQ_*D_/4)/256, 256>>>(v_features, out);
}

// round 6
// speedup vs baseline: 4.2203x; 1.2279x over previous
#include <cuda_runtime.h>
#include <cuda_fp16.h>
#include <stdint.h>
#include <math.h>

#define B_  2
#define N_  16384
#define M_  2048
#define D_  256
#define R_  (B_*N_)
#define RQ_ (B_*M_)
#define NSPLIT 8
#define KR_ (N_/NSPLIT)          // 2048 contraction per wv split
#define NMT 16                   // number of m-tiles (M_/128)
#define STAGE_BYTES 32768        // logits/proj: Ah(8K) Al(8K) Bh(8K) Bl(8K)
#define DYN_SMEM (3*STAGE_BYTES)
#define STAGE_WV 24576           // wv: Ah(8K) Bh(8K) Bl(8K)
#define DYN_SMEM_WV (3*STAGE_WV)

// ======================= device scratch =====================================
__device__ __align__(16) float  g_r[R_*3];
__device__ __align__(16) __half g_ph [(size_t)R_*D_],  g_pl [(size_t)R_*D_];
__device__ __align__(16) __half g_vfh[(size_t)RQ_*D_], g_vfl[(size_t)RQ_*D_];
__device__ __align__(16) __half g_wqTh[D_*D_], g_wqTl[D_*D_];
__device__ __align__(16) __half g_wkTh[D_*D_], g_wkTl[D_*D_];
__device__ __align__(16) __half g_wvTh[D_*D_], g_wvTl[D_*D_];
__device__ __align__(16) __half g_qh [(size_t)RQ_*D_], g_ql [(size_t)RQ_*D_];
__device__ __align__(16) __half g_kpvh[(size_t)R_*D_], g_kpvl[(size_t)R_*D_];
__device__ __align__(16) float  g_v[(size_t)R_*D_];
__device__ __align__(16) __half g_vth[(size_t)B_*D_*N_], g_vtl[(size_t)B_*D_*N_];
__device__ __align__(16) float  g_logits[(size_t)B_*M_*N_];   // 256 MB (scaled)
__device__ __align__(16) float  g_pmax[NMT*B_*N_], g_psum[NMT*B_*N_];
__device__ __align__(16) float  g_cstat[B_*N_];
__device__ __align__(16) float  g_part[(size_t)B_*NSPLIT*M_*D_];

// ======================= small helpers ======================================
__device__ __forceinline__ uint32_t smem_u32(const void* p) {
    uint32_t a;
    asm("{ .reg .u64 t; cvta.to.shared.u64 t, %1; cvt.u32.u64 %0, t; }" : "=r"(a) : "l"(p));
    return a;
}
__device__ __forceinline__ void cp16(uint32_t dst, const void* src) {
    asm volatile("cp.async.cg.shared.global [%0], [%1], 16;" :: "r"(dst), "l"(src));
}
#define CP_COMMIT() asm volatile("cp.async.commit_group;" ::: "memory")
#define CP_WAIT0()  asm volatile("cp.async.wait_group 0;" ::: "memory")
#define CP_WAIT1()  asm volatile("cp.async.wait_group 1;" ::: "memory")

__device__ __forceinline__ void ldsm_x4(uint32_t& r0, uint32_t& r1, uint32_t& r2, uint32_t& r3,
                                        uint32_t addr) {
    asm volatile("ldmatrix.sync.aligned.m8n8.x4.shared.b16 {%0,%1,%2,%3}, [%4];"
                 : "=r"(r0), "=r"(r1), "=r"(r2), "=r"(r3) : "r"(addr));
}
__device__ __forceinline__ void mma16816(float* c, const uint32_t* a, uint32_t b0, uint32_t b1) {
    asm volatile(
        "mma.sync.aligned.m16n8k16.row.col.f32.f16.f16.f32 "
        "{%0,%1,%2,%3}, {%4,%5,%6,%7}, {%8,%9}, {%0,%1,%2,%3};"
        : "+f"(c[0]), "+f"(c[1]), "+f"(c[2]), "+f"(c[3])
        : "r"(a[0]), "r"(a[1]), "r"(a[2]), "r"(a[3]), "r"(b0), "r"(b1));
}

// swizzled byte offset in a 128-row x 32-half tile (64B rows)
__device__ __forceinline__ uint32_t sw(int row, int c16) {
    return (uint32_t)(row * 64 + ((c16 ^ ((row ^ (row >> 2)) & 3)) << 4));
}

// fast exp, FFMA-only (no MUFU). Valid for x <= 0 (args here are always <= 0).
__device__ __forceinline__ float fexp(float x) {
    x = fmaxf(x, -80.0f);
    float nf = fmaf(x, 1.4426950408889634f, 12582912.0f);
    int  i   = __float_as_int(nf) - 0x4B400000;
    float n  = nf - 12582912.0f;
    float f  = fmaf(n, -0.693145751953125f, x);
    f        = fmaf(n, -1.42860682030941723e-6f, f);
    float p = 1.3888889e-3f;
    p = fmaf(p, f, 8.3333333e-3f);
    p = fmaf(p, f, 4.1666668e-2f);
    p = fmaf(p, f, 1.6666667e-1f);
    p = fmaf(p, f, 5.0e-1f);
    p = fmaf(p, f, 1.0f);
    p = fmaf(p, f, 1.0f);
    return p * __int_as_float((i + 127) << 23);
}

// ======================= 3-pass MMA stage compute ============================
// stage layout: Ah @ +0, Al @ +8192, Bh @ +16384, Bl @ +24576
__device__ __forceinline__ void compute_stage(uint32_t sb, int mw0, int nw0,
                                              float cacc[4][4][4], int lane) {
    int arow = lane & 15, asel = lane >> 4;
    int brow = (lane & 7) + ((lane >> 4) << 3), bsel = (lane >> 3) & 1;
#pragma unroll
    for (int ks = 0; ks < 2; ks++) {
        uint32_t ah[4][4], bh[2][4];
#pragma unroll
        for (int mi = 0; mi < 4; mi++)
            ldsm_x4(ah[mi][0], ah[mi][1], ah[mi][2], ah[mi][3],
                    sb + sw(mw0 + mi*16 + arow, ks*2 + asel));
#pragma unroll
        for (int nb = 0; nb < 2; nb++)
            ldsm_x4(bh[nb][0], bh[nb][1], bh[nb][2], bh[nb][3],
                    sb + 16384 + sw(nw0 + nb*16 + brow, ks*2 + bsel));
#pragma unroll
        for (int mi = 0; mi < 4; mi++)
#pragma unroll
            for (int nj = 0; nj < 4; nj++)
                mma16816(cacc[mi][nj], ah[mi], bh[nj>>1][(nj&1)*2], bh[nj>>1][(nj&1)*2+1]);

        uint32_t bl[2][4];
#pragma unroll
        for (int nb = 0; nb < 2; nb++)
            ldsm_x4(bl[nb][0], bl[nb][1], bl[nb][2], bl[nb][3],
                    sb + 24576 + sw(nw0 + nb*16 + brow, ks*2 + bsel));
#pragma unroll
        for (int mi = 0; mi < 4; mi++)
#pragma unroll
            for (int nj = 0; nj < 4; nj++)
                mma16816(cacc[mi][nj], ah[mi], bl[nj>>1][(nj&1)*2], bl[nj>>1][(nj&1)*2+1]);

        uint32_t al[4][4];
#pragma unroll
        for (int mi = 0; mi < 4; mi++)
            ldsm_x4(al[mi][0], al[mi][1], al[mi][2], al[mi][3],
                    sb + 8192 + sw(mw0 + mi*16 + arow, ks*2 + asel));
#pragma unroll
        for (int mi = 0; mi < 4; mi++)
#pragma unroll
            for (int nj = 0; nj < 4; nj++)
                mma16816(cacc[mi][nj], al[mi], bh[nj>>1][(nj&1)*2], bh[nj>>1][(nj&1)*2+1]);
    }
}

// ======================= 2-pass MMA stage (wv): Ah@0, Bh@8192, Bl@16384 ======
__device__ __forceinline__ void compute_stage_wv(uint32_t sb, int mw0, int nw0,
                                                 float cacc[4][4][4], int lane) {
    int arow = lane & 15, asel = lane >> 4;
    int brow = (lane & 7) + ((lane >> 4) << 3), bsel = (lane >> 3) & 1;
#pragma unroll
    for (int ks = 0; ks < 2; ks++) {
        uint32_t ah[4][4], bh[2][4], bl[2][4];
#pragma unroll
        for (int mi = 0; mi < 4; mi++)
            ldsm_x4(ah[mi][0], ah[mi][1], ah[mi][2], ah[mi][3],
                    sb + sw(mw0 + mi*16 + arow, ks*2 + asel));
#pragma unroll
        for (int nb = 0; nb < 2; nb++)
            ldsm_x4(bh[nb][0], bh[nb][1], bh[nb][2], bh[nb][3],
                    sb + 8192 + sw(nw0 + nb*16 + brow, ks*2 + bsel));
#pragma unroll
        for (int mi = 0; mi < 4; mi++)
#pragma unroll
            for (int nj = 0; nj < 4; nj++)
                mma16816(cacc[mi][nj], ah[mi], bh[nj>>1][(nj&1)*2], bh[nj>>1][(nj&1)*2+1]);
#pragma unroll
        for (int nb = 0; nb < 2; nb++)
            ldsm_x4(bl[nb][0], bl[nb][1], bl[nb][2], bl[nb][3],
                    sb + 16384 + sw(nw0 + nb*16 + brow, ks*2 + bsel));
#pragma unroll
        for (int mi = 0; mi < 4; mi++)
#pragma unroll
            for (int nj = 0; nj < 4; nj++)
                mma16816(cacc[mi][nj], ah[mi], bl[nj>>1][(nj&1)*2], bl[nj>>1][(nj&1)*2+1]);
    }
}

// cp.async staging of a full 3-pass stage (A hi/lo + B hi/lo)
__device__ __forceinline__ void stage4(uint32_t sb,
                                       const __half* __restrict__ Ah, const __half* __restrict__ Al,
                                       size_t ar0, int lda,
                                       const __half* __restrict__ Bh, const __half* __restrict__ Bl,
                                       size_t br0, int ldb, int k0) {
    int t = threadIdx.x;
#pragma unroll
    for (int i = 0; i < 2; i++) {
        int c = t + 256*i;
        int row = c >> 2, c16 = c & 3;
        uint32_t so = sw(row, c16);
        size_t ka = (size_t)k0 + c16*8;
        cp16(sb + so,         Ah + (ar0 + row)*(size_t)lda + ka);
        cp16(sb + 8192 + so,  Al + (ar0 + row)*(size_t)lda + ka);
        cp16(sb + 16384 + so, Bh + (br0 + row)*(size_t)ldb + ka);
        cp16(sb + 24576 + so, Bl + (br0 + row)*(size_t)ldb + ka);
    }
}

// ======================= K0: positional path ================================
__global__ void pv_relu_kernel(const float* __restrict__ p_xyz, const float* __restrict__ v_xyz,
                               const float* __restrict__ Wp1, const float* __restrict__ bp1,
                               const float* __restrict__ ln_w, const float* __restrict__ ln_b) {
    int idx = blockIdx.x * blockDim.x + threadIdx.x;
    if (idx >= R_) return;
    int b = idx / N_;
    float d0 = fabsf(p_xyz[idx*3+0] - v_xyz[b*3+0]);
    float d1 = fabsf(p_xyz[idx*3+1] - v_xyz[b*3+1]);
    float d2 = fabsf(p_xyz[idx*3+2] - v_xyz[b*3+2]);
    float h0 = d0*Wp1[0] + d1*Wp1[3] + d2*Wp1[6] + bp1[0];
    float h1 = d0*Wp1[1] + d1*Wp1[4] + d2*Wp1[7] + bp1[1];
    float h2 = d0*Wp1[2] + d1*Wp1[5] + d2*Wp1[8] + bp1[2];
    float mu = (h0 + h1 + h2) * (1.0f/3.0f);
    float e0 = h0-mu, e1 = h1-mu, e2 = h2-mu;
    float inv = rsqrtf((e0*e0 + e1*e1 + e2*e2) * (1.0f/3.0f) + 1e-5f);
    g_r[idx*3+0] = fmaxf(e0*inv*ln_w[0] + ln_b[0], 0.0f);
    g_r[idx*3+1] = fmaxf(e1*inv*ln_w[1] + ln_b[1], 0.0f);
    g_r[idx*3+2] = fmaxf(e2*inv*ln_w[2] + ln_b[2], 0.0f);
}

// ======================= prep: all hi/lo splits (one launch) =================
#define NP2 ((size_t)R_*D_/2)
#define NV2 ((size_t)RQ_*D_/2)
__global__ void splitall_kernel(const float* __restrict__ P, const float* __restrict__ VF) {
    size_t i = (size_t)blockIdx.x * blockDim.x + threadIdx.x;
    const float* src; __half *hi, *lo; size_t j;
    if (i < NP2)                 { src = P;  hi = g_ph;  lo = g_pl;  j = i; }
    else if (i < NP2 + NV2)      { src = VF; hi = g_vfh; lo = g_vfl; j = i - NP2; }
    else return;
    float2 v = reinterpret_cast<const float2*>(src)[j];
    __half h0 = __float2half_rn(v.x), h1 = __float2half_rn(v.y);
    __half l0 = __float2half_rn(v.x - __half2float(h0));
    __half l1 = __float2half_rn(v.y - __half2float(h1));
    reinterpret_cast<__half2*>(hi)[j] = __halves2half2(h0, h1);
    reinterpret_cast<__half2*>(lo)[j] = __halves2half2(l0, l1);
}

__global__ void wtsplitall_kernel(const float* __restrict__ Wq, const float* __restrict__ Wk,
                                  const float* __restrict__ Wv) {
    int i = blockIdx.x * blockDim.x + threadIdx.x;   // 3*65536
    int w = i >> 16, rem = i & 65535;
    int d = rem >> 8, c = rem & 255;
    const float* W = (w == 0) ? Wq : (w == 1) ? Wk : Wv;
    __half* Th = (w == 0) ? g_wqTh : (w == 1) ? g_wkTh : g_wvTh;
    __half* Tl = (w == 0) ? g_wqTl : (w == 1) ? g_wkTl : g_wvTl;
    float v = W[rem];
    __half h = __float2half_rn(v);
    Th[c*256 + d] = h;
    Tl[c*256 + d] = __float2half_rn(v - __half2float(h));
}

// ======================= fused projections (HMMA, one launch) ================
// z=0: q = vf@Wq + bq -> qh/ql ; z=1: kpv = p@Wk + bk + pv ; z=2: v (fp32)
__global__ __launch_bounds__(256, 2)
void proj_mma_kernel(const float* __restrict__ bq, const float* __restrict__ bk,
                     const float* __restrict__ bv, const float* __restrict__ Wp2,
                     const float* __restrict__ bp2) {
    int mode = blockIdx.z;
    if (mode == 0 && blockIdx.y >= RQ_/128) return;
    extern __shared__ char dyn[];
    uint32_t sb = smem_u32(dyn);
    const __half *Xh, *Xl, *WTh, *WTl; const float* bias;
    if (mode == 0)      { Xh = g_vfh; Xl = g_vfl; WTh = g_wqTh; WTl = g_wqTl; bias = bq; }
    else if (mode == 1) { Xh = g_ph;  Xl = g_pl;  WTh = g_wkTh; WTl = g_wkTl; bias = bk; }
    else                { Xh = g_ph;  Xl = g_pl;  WTh = g_wvTh; WTl = g_wvTl; bias = bv; }

    size_t row0 = (size_t)blockIdx.y * 128;
    int c0 = blockIdx.x * 128;
    int lane = threadIdx.x & 31, wid = threadIdx.x >> 5;
    int mw0 = (wid >> 2) * 64, nw0 = (wid & 3) * 32;
    float cacc[4][4][4] = {};

    stage4(sb + 0*STAGE_BYTES, Xh, Xl, row0, D_, WTh, WTl, (size_t)c0, D_, 0);  CP_COMMIT();
    stage4(sb + 1*STAGE_BYTES, Xh, Xl, row0, D_, WTh, WTl, (size_t)c0, D_, 32); CP_COMMIT();
#pragma unroll 1
    for (int s = 0; s < 8; s++) {
        if (s < 7) CP_WAIT1(); else CP_WAIT0();
        __syncthreads();
        if (s + 2 < 8) {
            stage4(sb + ((s+2)%3)*STAGE_BYTES, Xh, Xl, row0, D_, WTh, WTl, (size_t)c0, D_, (s+2)*32);
            CP_COMMIT();
        }
        compute_stage(sb + (s%3)*STAGE_BYTES, mw0, nw0, cacc, lane);
    }

    int g = lane >> 2, tg = lane & 3;
#pragma unroll
    for (int mi = 0; mi < 4; mi++) {
#pragma unroll
        for (int half_m = 0; half_m < 2; half_m++) {
            size_t r = row0 + mw0 + mi*16 + g + half_m*8;
            float q0 = 0.f, q1 = 0.f, q2 = 0.f;
            if (mode == 1) { q0 = g_r[r*3+0]; q1 = g_r[r*3+1]; q2 = g_r[r*3+2]; }
#pragma unroll
            for (int nj = 0; nj < 4; nj++) {
#pragma unroll
                for (int e = 0; e < 2; e++) {
                    int c = c0 + nw0 + nj*8 + tg*2 + e;
                    float v = cacc[mi][nj][half_m*2 + e] + bias[c];
                    if (mode == 1) v += q0*Wp2[c] + q1*Wp2[D_+c] + q2*Wp2[2*D_+c] + bp2[c];
                    if (mode == 2) { g_v[r*D_ + c] = v; }
                    else {
                        __half h = __float2half_rn(v);
                        __half l = __float2half_rn(v - __half2float(h));
                        if (mode == 0) { g_qh[r*D_+c] = h;   g_ql[r*D_+c] = l; }
                        else           { g_kpvh[r*D_+c] = h; g_kpvl[r*D_+c] = l; }
                    }
                }
            }
        }
    }
}

// ======================= V transpose + split =================================
__global__ void vtrans_kernel() {
    __shared__ float tl[32][33];
    int n0 = blockIdx.x * 32, d0 = blockIdx.y * 32, b = blockIdx.z;
    int tx = threadIdx.x, ty = threadIdx.y;
#pragma unroll
    for (int k = 0; k < 4; k++)
        tl[ty + k*8][tx] = g_v[(size_t)(b*N_ + n0 + ty + k*8)*D_ + d0 + tx];
    __syncthreads();
#pragma unroll
    for (int k = 0; k < 4; k++) {
        int d = d0 + ty + k*8;
        float v = tl[tx][ty + k*8];
        __half h = __float2half_rn(v);
        size_t o = (size_t)(b*D_ + d)*N_ + n0 + tx;
        g_vth[o] = h;
        g_vtl[o] = __float2half_rn(v - __half2float(h));
    }
}

// ======================= logits (HMMA) + fused partial softmax stats =========
__global__ __launch_bounds__(256, 2)
void logits_mma_kernel() {
    extern __shared__ char dyn[];
    uint32_t sb = smem_u32(dyn);
    int b = blockIdx.z;
    int n0 = blockIdx.x * 128, m0 = blockIdx.y * 128;
    size_t ar0 = (size_t)b*M_ + m0, br0 = (size_t)b*N_ + n0;
    int lane = threadIdx.x & 31, wid = threadIdx.x >> 5;
    int mw0 = (wid >> 2) * 64, nw0 = (wid & 3) * 32;
    float cacc[4][4][4] = {};

    stage4(sb + 0*STAGE_BYTES, g_qh, g_ql, ar0, D_, g_kpvh, g_kpvl, br0, D_, 0);  CP_COMMIT();
    stage4(sb + 1*STAGE_BYTES, g_qh, g_ql, ar0, D_, g_kpvh, g_kpvl, br0, D_, 32); CP_COMMIT();
#pragma unroll 1
    for (int s = 0; s < 8; s++) {
        if (s < 7) CP_WAIT1(); else CP_WAIT0();
        __syncthreads();
        if (s + 2 < 8) {
            stage4(sb + ((s+2)%3)*STAGE_BYTES, g_qh, g_ql, ar0, D_, g_kpvh, g_kpvl, br0, D_, (s+2)*32);
            CP_COMMIT();
        }
        compute_stage(sb + (s%3)*STAGE_BYTES, mw0, nw0, cacc, lane);
    }

    // scale accumulators (logits are stored pre-scaled)
#pragma unroll
    for (int mi = 0; mi < 4; mi++)
#pragma unroll
        for (int nj = 0; nj < 4; nj++)
#pragma unroll
            for (int e = 0; e < 4; e++) cacc[mi][nj][e] *= 0.0625f;

    int g = lane >> 2, tg = lane & 3;
    float* L = g_logits + (size_t)b*M_*N_;
#pragma unroll
    for (int mi = 0; mi < 4; mi++)
#pragma unroll
        for (int nj = 0; nj < 4; nj++) {
            int m = m0 + mw0 + mi*16 + g;
            int n = n0 + nw0 + nj*8 + tg*2;
            float2 v0 = { cacc[mi][nj][0], cacc[mi][nj][1] };
            float2 v1 = { cacc[mi][nj][2], cacc[mi][nj][3] };
            *reinterpret_cast<float2*>(&L[(size_t)m*N_ + n])     = v0;
            *reinterpret_cast<float2*>(&L[(size_t)(m+8)*N_ + n]) = v1;
        }

    // per-column (over 128 m rows of this tile) max + sumexp partials
    __syncthreads();              // smem (dyn) free for reuse now
    float* smax = reinterpret_cast<float*>(dyn);        // [2][128]
    float* ssum = smax + 256;                            // [2][128]
#pragma unroll
    for (int nj = 0; nj < 4; nj++) {
#pragma unroll
        for (int ec = 0; ec < 2; ec++) {
            float mx = -1e30f;
#pragma unroll
            for (int mi = 0; mi < 4; mi++) {
                mx = fmaxf(mx, cacc[mi][nj][ec]);
                mx = fmaxf(mx, cacc[mi][nj][2 + ec]);
            }
            mx = fmaxf(mx, __shfl_xor_sync(0xFFFFFFFFu, mx, 4));
            mx = fmaxf(mx, __shfl_xor_sync(0xFFFFFFFFu, mx, 8));
            mx = fmaxf(mx, __shfl_xor_sync(0xFFFFFFFFu, mx, 16));
            float s = 0.0f;
#pragma unroll
            for (int mi = 0; mi < 4; mi++) {
                s += fexp(cacc[mi][nj][ec]     - mx);
                s += fexp(cacc[mi][nj][2 + ec] - mx);
            }
            s += __shfl_xor_sync(0xFFFFFFFFu, s, 4);
            s += __shfl_xor_sync(0xFFFFFFFFu, s, 8);
            s += __shfl_xor_sync(0xFFFFFFFFu, s, 16);
            if (g == 0) {
                int nc = (wid & 3)*32 + nj*8 + tg*2 + ec;
                smax[(wid >> 2)*128 + nc] = mx;
                ssum[(wid >> 2)*128 + nc] = s;
            }
        }
    }
    __syncthreads();
    int t = threadIdx.x;
    if (t < 128) {
        float m0v = smax[t], m1v = smax[128 + t];
        float s0  = ssum[t], s1  = ssum[128 + t];
        float mm = fmaxf(m0v, m1v);
        float ss = s0 * fexp(m0v - mm) + s1 * fexp(m1v - mm);
        int col = b*N_ + n0 + t;
        g_pmax[blockIdx.y*(B_*N_) + col] = mm;
        g_psum[blockIdx.y*(B_*N_) + col] = ss;
    }
}

// ======================= stats reduce over m-tiles ===========================
__global__ void cstat_reduce_kernel() {
    int col = blockIdx.x * blockDim.x + threadIdx.x;   // 0..B*N-1
    float mx = -1e30f, sum = 0.0f;
#pragma unroll
    for (int ti = 0; ti < NMT; ti++) {
        float m2 = g_pmax[ti*(B_*N_) + col];
        float s2 = g_psum[ti*(B_*N_) + col];
        if (m2 > mx) { sum = sum * fexp(mx - m2) + s2; mx = m2; }
        else         { sum += s2 * fexp(m2 - mx); }
    }
    g_cstat[col] = mx + __logf(sum);
}

// ======================= weighted value (HMMA 2-pass, split-K, fused exp) ====
__global__ __launch_bounds__(256, 2)
void wv_mma_kernel() {
    extern __shared__ char dyn[];
    uint32_t sb = smem_u32(dyn);
    int z = blockIdx.z, b = z >> 3, sp = z & 7;
    int d0 = blockIdx.x * 128, m0 = blockIdx.y * 128;
    int kbeg = sp * KR_;
    const float* L  = g_logits + (size_t)b*M_*N_;
    const float* CS = g_cstat + b*N_;
    size_t br0 = (size_t)b*D_ + d0;
    int t = threadIdx.x, lane = t & 31, wid = t >> 5;
    int mw0 = (wid >> 2) * 64, nw0 = (wid & 3) * 32;
    float cacc[4][4][4] = {};

    int rows[2], c16s[2];
#pragma unroll
    for (int i = 0; i < 2; i++) { int c = t + 256*i; rows[i] = c >> 2; c16s[i] = c & 3; }

    float4 ra[2][2];
    // prologue: LDG A(0); cp.async B(0), B(1)
#pragma unroll
    for (int i = 0; i < 2; i++) {
        size_t base = (size_t)(m0 + rows[i])*N_ + kbeg + c16s[i]*8;
        ra[i][0] = *reinterpret_cast<const float4*>(&L[base]);
        ra[i][1] = *reinterpret_cast<const float4*>(&L[base + 4]);
    }
#pragma unroll
    for (int st = 0; st < 2; st++) {
        uint32_t bufB = sb + st*STAGE_WV;
#pragma unroll
        for (int i = 0; i < 2; i++) {
            uint32_t so = sw(rows[i], c16s[i]);
            size_t ka = (size_t)(kbeg + st*32) + c16s[i]*8;
            cp16(bufB + 8192  + so, g_vth + (br0 + rows[i])*(size_t)N_ + ka);
            cp16(bufB + 16384 + so, g_vtl + (br0 + rows[i])*(size_t)N_ + ka);
        }
        CP_COMMIT();
    }

    const int NCH = KR_ / 32;   // 64
#pragma unroll 1
    for (int s = 0; s < NCH; s++) {
        uint32_t buf  = sb + (s%3)*STAGE_WV;
        char*    bufp = dyn + (s%3)*STAGE_WV;
        if (s < NCH-1) CP_WAIT1(); else CP_WAIT0();
        // transform + STS A(s): weights hi only (2-pass drops w_lo)
#pragma unroll
        for (int i = 0; i < 2; i++) {
            int kabs = kbeg + s*32 + c16s[i]*8;
            float4 cs0 = *reinterpret_cast<const float4*>(&CS[kabs]);
            float4 cs1 = *reinterpret_cast<const float4*>(&CS[kabs + 4]);
            float w[8];
            w[0] = fexp(ra[i][0].x - cs0.x); w[1] = fexp(ra[i][0].y - cs0.y);
            w[2] = fexp(ra[i][0].z - cs0.z); w[3] = fexp(ra[i][0].w - cs0.w);
            w[4] = fexp(ra[i][1].x - cs1.x); w[5] = fexp(ra[i][1].y - cs1.y);
            w[6] = fexp(ra[i][1].z - cs1.z); w[7] = fexp(ra[i][1].w - cs1.w);
            uint32_t hi[4];
#pragma unroll
            for (int j = 0; j < 4; j++) {
                __half h0 = __float2half_rn(w[2*j]), h1 = __float2half_rn(w[2*j+1]);
                hi[j] = (uint32_t)__half_as_ushort(h0) | ((uint32_t)__half_as_ushort(h1) << 16);
            }
            uint32_t so = sw(rows[i], c16s[i]);
            *reinterpret_cast<uint4*>(bufp + so) = make_uint4(hi[0], hi[1], hi[2], hi[3]);
        }
        __syncthreads();
        if (s + 1 < NCH) {
            int kn = kbeg + (s+1)*32;
#pragma unroll
            for (int i = 0; i < 2; i++) {
                size_t base = (size_t)(m0 + rows[i])*N_ + kn + c16s[i]*8;
                ra[i][0] = *reinterpret_cast<const float4*>(&L[base]);
                ra[i][1] = *reinterpret_cast<const float4*>(&L[base + 4]);
            }
        }
        if (s + 2 < NCH) {
            uint32_t nbuf = sb + ((s+2)%3)*STAGE_WV;
            int kn2 = kbeg + (s+2)*32;
#pragma unroll
            for (int i = 0; i < 2; i++) {
                uint32_t so = sw(rows[i], c16s[i]);
                size_t ka = (size_t)kn2 + c16s[i]*8;
                cp16(nbuf + 8192  + so, g_vth + (br0 + rows[i])*(size_t)N_ + ka);
                cp16(nbuf + 16384 + so, g_vtl + (br0 + rows[i])*(size_t)N_ + ka);
            }
            CP_COMMIT();
        }
        compute_stage_wv(buf, mw0, nw0, cacc, lane);
    }

    int g = lane >> 2, tg = lane & 3;
    float* P = g_part + (size_t)z*M_*D_;
#pragma unroll
    for (int mi = 0; mi < 4; mi++)
#pragma unroll
        for (int nj = 0; nj < 4; nj++) {
            int m = m0 + mw0 + mi*16 + g;
            int d = d0 + nw0 + nj*8 + tg*2;
            float2 v0 = { cacc[mi][nj][0], cacc[mi][nj][1] };
            float2 v1 = { cacc[mi][nj][2], cacc[mi][nj][3] };
            *reinterpret_cast<float2*>(&P[(size_t)m*D_ + d])     = v0;
            *reinterpret_cast<float2*>(&P[(size_t)(m+8)*D_ + d]) = v1;
        }
}

// ======================= reduce + residual ===================================
__global__ void reduce_kernel(const float* __restrict__ Vf, float* __restrict__ out) {
    int i4 = blockIdx.x * blockDim.x + threadIdx.x;   // RQ_*D_/4
    int row = i4 >> 6;
    int b = row >> 11;
    int mrow = row & (M_ - 1);
    int d4 = i4 & 63;
    float4 acc = reinterpret_cast<const float4*>(Vf)[i4];
#pragma unroll
    for (int s = 0; s < NSPLIT; s++) {
        size_t pi = ((size_t)(b*NSPLIT + s)*M_ + mrow)*64 + d4;
        float4 p = reinterpret_cast<const float4*>(g_part)[pi];
        acc.x += p.x; acc.y += p.y; acc.z += p.z; acc.w += p.w;
    }
    reinterpret_cast<float4*>(out)[i4] = acc;
}

// ======================= launcher ============================================
extern "C" void kernel_launch(void* const* d_in, const int* in_sizes, int n_in,
                              void* d_out, int out_size) {
    const float* p_xyz      = (const float*)d_in[0];
    const float* v_xyz      = (const float*)d_in[1];
    const float* p_features = (const float*)d_in[2];
    const float* v_features = (const float*)d_in[3];
    const float* Wq  = (const float*)d_in[4];
    const float* bq  = (const float*)d_in[5];
    const float* Wk  = (const float*)d_in[6];
    const float* bk  = (const float*)d_in[7];
    const float* Wv  = (const float*)d_in[8];
    const float* bv  = (const float*)d_in[9];
    const float* Wp1 = (const float*)d_in[10];
    const float* bp1 = (const float*)d_in[11];
    const float* ln_w = (const float*)d_in[12];
    const float* ln_b = (const float*)d_in[13];
    const float* Wp2 = (const float*)d_in[14];
    const float* bp2 = (const float*)d_in[15];
    float* out = (float*)d_out;

    static int attr_done = 0;
    if (!attr_done) {
        cudaFuncSetAttribute(proj_mma_kernel,   cudaFuncAttributeMaxDynamicSharedMemorySize, DYN_SMEM);
        cudaFuncSetAttribute(logits_mma_kernel, cudaFuncAttributeMaxDynamicSharedMemorySize, DYN_SMEM);
        cudaFuncSetAttribute(wv_mma_kernel,     cudaFuncAttributeMaxDynamicSharedMemorySize, DYN_SMEM_WV);
        attr_done = 1;
    }

    // [0] input hi/lo splits (p_features + v_features, one launch)
    splitall_kernel<<<(unsigned)((NP2 + NV2 + 255)/256), 256>>>(p_features, v_features);
    // [1] weight transpose+split (all three, one launch)
    wtsplitall_kernel<<<768, 256>>>(Wq, Wk, Wv);
    // [2] positional path
    pv_relu_kernel<<<R_/256, 256>>>(p_xyz, v_xyz, Wp1, bp1, ln_w, ln_b);
    // [3] fused projections q/k/v
    proj_mma_kernel<<<dim3(2, R_/128, 3), 256, DYN_SMEM>>>(bq, bk, bv, Wp2, bp2);
    // [4] V transpose + split
    vtrans_kernel<<<dim3(N_/32, D_/32, B_), dim3(32, 8)>>>();
    // [5] logits + fused partial stats   <-- ncu -s 5 -c 1 lands here
    logits_mma_kernel<<<dim3(N_/128, M_/128, B_), 256, DYN_SMEM>>>();
    // [6] stats reduce
    cstat_reduce_kernel<<<(B_*N_)/256, 256>>>();
    // [7] weighted value (2-pass, split-K)
    wv_mma_kernel<<<dim3(D_/128, M_/128, B_*NSPLIT), 256, DYN_SMEM_WV>>>();
    // [8] reduce + residual
    reduce_kernel<<<(RQ_*D_/4)/256, 256>>>(v_features, out);
}